// round 1
// baseline (speedup 1.0000x reference)
#include <cuda_runtime.h>
#include <math.h>

#define NNODES 4096
#define TN2    8192
#define DIM    128
#define FDIM   256
#define NEDGE  65536

// ---------------- scratch (no allocation allowed) ----------------
__device__ float g_X[TN2 * DIM];
__device__ float g_Kb[TN2 * DIM];
__device__ float g_Vb[TN2 * DIM];
__device__ float g_Qb[TN2 * DIM];
__device__ float g_Ob[TN2 * DIM];
__device__ float g_F[TN2 * FDIM];
__device__ float g_AGG[TN2 * FDIM];
__device__ float g_MEAN[TN2 * FDIM];
__device__ float g_DEG[TN2];

// ---------------- small elementwise kernels ----------------
__global__ void concat_x(const float* __restrict__ x1, const float* __restrict__ x2,
                         float* __restrict__ X) {
    int i = blockIdx.x * blockDim.x + threadIdx.x;
    if (i < TN2 * DIM)
        X[i] = (i < NNODES * DIM) ? x1[i] : x2[i - NNODES * DIM];
}

__global__ void zero_f(float* __restrict__ p, int n) {
    int i = blockIdx.x * blockDim.x + threadIdx.x;
    if (i < n) p[i] = 0.f;
}

__global__ void deg_count(const int* __restrict__ ei, int off, float* __restrict__ deg) {
    int e = blockIdx.x * blockDim.x + threadIdx.x;
    if (e < NEDGE) atomicAdd(&deg[ei[NEDGE + e] + off], 1.0f);
}

__global__ void scatter_add(const float* __restrict__ feats, const int* __restrict__ ei,
                            int off, float* __restrict__ agg) {
    int e = blockIdx.x;
    int src = ei[e] + off;
    int dst = ei[NEDGE + e] + off;
    atomicAdd(&agg[dst * FDIM + threadIdx.x], feats[src * FDIM + threadIdx.x]);
}

__global__ void build_feats(const float* __restrict__ X, const float* __restrict__ O,
                            float* __restrict__ F) {
    int i = blockIdx.x * blockDim.x + threadIdx.x;
    if (i < TN2 * DIM) {
        int row = i >> 7, c = i & 127;
        float x = X[i];
        F[row * FDIM + c] = x;
        F[row * FDIM + DIM + c] = x - O[i];
    }
}

__global__ void mean_div(const float* __restrict__ agg, const float* __restrict__ deg,
                         float* __restrict__ mean) {
    int i = blockIdx.x * blockDim.x + threadIdx.x;
    if (i < TN2 * FDIM) {
        int row = i >> 8;
        mean[i] = agg[i] / fmaxf(deg[row], 1.0f);
    }
}

// ---------------- generic GEMM: C[M,128] = A[M,K] @ B[K,128] (+bias)(+acc)(+relu) ----
// block: 64 rows x 128 cols, 256 threads, 4x8 per thread. M = gridDim.x*64.
#define FL_RELU 1
#define FL_ACC  2
__global__ void gemm_n128(const float* __restrict__ A, const float* __restrict__ B,
                          const float* __restrict__ bias, float* __restrict__ C,
                          int K, int flags) {
    __shared__ float As[16 * 65];   // [k][m], stride 65
    __shared__ float Bs[16 * 128];  // [k][n]
    int tid = threadIdx.x;
    int tx = tid & 15, ty = tid >> 4;
    int m0 = blockIdx.x * 64;
    int arow = tid >> 2, akq = tid & 3;
    int brow = tid >> 5, bcol = (tid & 31) * 4;
    float acc[4][8];
#pragma unroll
    for (int i = 0; i < 4; i++)
#pragma unroll
        for (int j = 0; j < 8; j++) acc[i][j] = 0.f;

    for (int kt = 0; kt < K; kt += 16) {
        float4 av = *(const float4*)&A[(m0 + arow) * K + kt + akq * 4];
        As[(akq * 4 + 0) * 65 + arow] = av.x;
        As[(akq * 4 + 1) * 65 + arow] = av.y;
        As[(akq * 4 + 2) * 65 + arow] = av.z;
        As[(akq * 4 + 3) * 65 + arow] = av.w;
        *(float4*)&Bs[brow * 128 + bcol] = *(const float4*)&B[(kt + brow) * 128 + bcol];
        *(float4*)&Bs[(brow + 8) * 128 + bcol] = *(const float4*)&B[(kt + brow + 8) * 128 + bcol];
        __syncthreads();
#pragma unroll
        for (int kk = 0; kk < 16; kk++) {
            float a[4], b[8];
#pragma unroll
            for (int i = 0; i < 4; i++) a[i] = As[kk * 65 + ty + 16 * i];
#pragma unroll
            for (int j = 0; j < 8; j++) b[j] = Bs[kk * 128 + tx + 16 * j];
#pragma unroll
            for (int i = 0; i < 4; i++)
#pragma unroll
                for (int j = 0; j < 8; j++) acc[i][j] += a[i] * b[j];
        }
        __syncthreads();
    }
#pragma unroll
    for (int i = 0; i < 4; i++)
#pragma unroll
        for (int j = 0; j < 8; j++) {
            float v = acc[i][j];
            if (bias) v += bias[tx + 16 * j];
            int idx = (m0 + ty + 16 * i) * 128 + tx + 16 * j;
            if (flags & FL_ACC) v += C[idx];
            if (flags & FL_RELU) v = fmaxf(v, 0.f);
            C[idx] = v;
        }
}

// ---------------- flash attention: Nq=Nk=8192, d=dv=128, fp32 ----------------
// block: 64 queries, 256 threads; loops 64-key tiles with online softmax.
#define QS 132           // padded row stride for 128-float rows
#define SSTR 68          // padded stride for the 64x64 S tile
#define FLASH_SMEM ((3 * 64 * QS + 64 * SSTR + 3 * 64) * 4)

__global__ void flash_attn(const float* __restrict__ Q, const float* __restrict__ Kp,
                           const float* __restrict__ Vp, float* __restrict__ Out) {
    extern __shared__ float sm[];
    float* Qs = sm;
    float* Ks = Qs + 64 * QS;
    float* Vs = Ks + 64 * QS;
    float* Ss = Vs + 64 * QS;
    float* m_s = Ss + 64 * SSTR;
    float* l_s = m_s + 64;
    float* corr_s = l_s + 64;

    int tid = threadIdx.x;
    int tx = tid & 15, ty = tid >> 4;
    int q0 = blockIdx.x * 64;
    const float isc = 0.08838834764831845f;  // 1/sqrt(128)

#pragma unroll
    for (int rep = 0; rep < 8; rep++) {
        int idx = rep * 256 + tid;
        int row = idx >> 5;
        int c4 = (idx & 31) * 4;
        float4 v = *(const float4*)&Q[(q0 + row) * 128 + c4];
        v.x *= isc; v.y *= isc; v.z *= isc; v.w *= isc;
        *(float4*)&Qs[row * QS + c4] = v;
    }
    if (tid < 64) { m_s[tid] = -1e30f; l_s[tid] = 0.f; }
    float acc[4][8];
#pragma unroll
    for (int i = 0; i < 4; i++)
#pragma unroll
        for (int j = 0; j < 8; j++) acc[i][j] = 0.f;
    __syncthreads();

    for (int k0 = 0; k0 < TN2; k0 += 64) {
#pragma unroll
        for (int rep = 0; rep < 8; rep++) {
            int idx = rep * 256 + tid;
            int row = idx >> 5;
            int c4 = (idx & 31) * 4;
            *(float4*)&Ks[row * QS + c4] = *(const float4*)&Kp[(k0 + row) * 128 + c4];
            *(float4*)&Vs[row * QS + c4] = *(const float4*)&Vp[(k0 + row) * 128 + c4];
        }
        __syncthreads();

        // S[64x64] = Qs @ Ks^T ; thread -> rows ty+16i, cols tx+16j (j<4)
        float s[4][4];
#pragma unroll
        for (int i = 0; i < 4; i++)
#pragma unroll
            for (int j = 0; j < 4; j++) s[i][j] = 0.f;
#pragma unroll 4
        for (int c = 0; c < 128; c++) {
            float qa[4], kb[4];
#pragma unroll
            for (int i = 0; i < 4; i++) qa[i] = Qs[(ty + 16 * i) * QS + c];
#pragma unroll
            for (int j = 0; j < 4; j++) kb[j] = Ks[(tx + 16 * j) * QS + c];
#pragma unroll
            for (int i = 0; i < 4; i++)
#pragma unroll
                for (int j = 0; j < 4; j++) s[i][j] += qa[i] * kb[j];
        }
#pragma unroll
        for (int i = 0; i < 4; i++)
#pragma unroll
            for (int j = 0; j < 4; j++)
                Ss[(ty + 16 * i) * SSTR + tx + 16 * j] = s[i][j];
        __syncthreads();

        // online softmax: 4 lanes per row
        {
            int r = tid >> 2, qd = tid & 3;
            float tmax = -1e30f;
#pragma unroll
            for (int kk = 0; kk < 16; kk++)
                tmax = fmaxf(tmax, Ss[r * SSTR + qd * 16 + kk]);
            tmax = fmaxf(tmax, __shfl_xor_sync(0xffffffffu, tmax, 1));
            tmax = fmaxf(tmax, __shfl_xor_sync(0xffffffffu, tmax, 2));
            float mold = m_s[r];
            float mnew = fmaxf(mold, tmax);
            float psum = 0.f;
#pragma unroll
            for (int kk = 0; kk < 16; kk++) {
                float p = __expf(Ss[r * SSTR + qd * 16 + kk] - mnew);
                Ss[r * SSTR + qd * 16 + kk] = p;
                psum += p;
            }
            psum += __shfl_xor_sync(0xffffffffu, psum, 1);
            psum += __shfl_xor_sync(0xffffffffu, psum, 2);
            if (qd == 0) {
                float corr = __expf(mold - mnew);
                corr_s[r] = corr;
                l_s[r] = l_s[r] * corr + psum;
                m_s[r] = mnew;
            }
        }
        __syncthreads();

        // O += P @ V
        float cr[4];
#pragma unroll
        for (int i = 0; i < 4; i++) cr[i] = corr_s[ty + 16 * i];
#pragma unroll
        for (int i = 0; i < 4; i++)
#pragma unroll
            for (int j = 0; j < 8; j++) acc[i][j] *= cr[i];
#pragma unroll 4
        for (int kk = 0; kk < 64; kk++) {
            float p[4], v[8];
#pragma unroll
            for (int i = 0; i < 4; i++) p[i] = Ss[(ty + 16 * i) * SSTR + kk];
#pragma unroll
            for (int j = 0; j < 8; j++) v[j] = Vs[kk * QS + tx + 16 * j];
#pragma unroll
            for (int i = 0; i < 4; i++)
#pragma unroll
                for (int j = 0; j < 8; j++) acc[i][j] += p[i] * v[j];
        }
        __syncthreads();
    }

    float linv[4];
#pragma unroll
    for (int i = 0; i < 4; i++) linv[i] = 1.f / l_s[ty + 16 * i];
#pragma unroll
    for (int i = 0; i < 4; i++)
#pragma unroll
        for (int j = 0; j < 8; j++)
            Out[(q0 + ty + 16 * i) * 128 + tx + 16 * j] = acc[i][j] * linv[i];
}

// ---------------- final: C[8192,8192] = sigmoid(F @ F^T), K=128 ----------------
__global__ void gemm_nt_sigmoid(const float* __restrict__ F, float* __restrict__ C) {
    __shared__ float As[16 * 65];   // [k][m]
    __shared__ float Bs[16 * 132];  // [k][n]
    int tid = threadIdx.x;
    int tx = tid & 15, ty = tid >> 4;
    int m0 = blockIdx.x * 64;
    int n0 = blockIdx.y * 128;
    int arow = tid >> 2, akq = tid & 3;
    float acc[4][8];
#pragma unroll
    for (int i = 0; i < 4; i++)
#pragma unroll
        for (int j = 0; j < 8; j++) acc[i][j] = 0.f;

    for (int kt = 0; kt < 128; kt += 16) {
        float4 av = *(const float4*)&F[(m0 + arow) * 128 + kt + akq * 4];
        As[(akq * 4 + 0) * 65 + arow] = av.x;
        As[(akq * 4 + 1) * 65 + arow] = av.y;
        As[(akq * 4 + 2) * 65 + arow] = av.z;
        As[(akq * 4 + 3) * 65 + arow] = av.w;
#pragma unroll
        for (int rep = 0; rep < 2; rep++) {
            int idx = rep * 256 + tid;
            int row = idx >> 2, kq = idx & 3;
            float4 bv = *(const float4*)&F[(n0 + row) * 128 + kt + kq * 4];
            Bs[(kq * 4 + 0) * 132 + row] = bv.x;
            Bs[(kq * 4 + 1) * 132 + row] = bv.y;
            Bs[(kq * 4 + 2) * 132 + row] = bv.z;
            Bs[(kq * 4 + 3) * 132 + row] = bv.w;
        }
        __syncthreads();
#pragma unroll
        for (int kk = 0; kk < 16; kk++) {
            float a[4], b[8];
#pragma unroll
            for (int i = 0; i < 4; i++) a[i] = As[kk * 65 + ty + 16 * i];
#pragma unroll
            for (int j = 0; j < 8; j++) b[j] = Bs[kk * 132 + tx + 16 * j];
#pragma unroll
            for (int i = 0; i < 4; i++)
#pragma unroll
                for (int j = 0; j < 8; j++) acc[i][j] += a[i] * b[j];
        }
        __syncthreads();
    }
#pragma unroll
    for (int i = 0; i < 4; i++)
#pragma unroll
        for (int j = 0; j < 8; j++) {
            float v = 1.f / (1.f + __expf(-acc[i][j]));
            C[(size_t)(m0 + ty + 16 * i) * TN2 + n0 + tx + 16 * j] = v;
        }
}

// ---------------- host orchestration ----------------
extern "C" void kernel_launch(void* const* d_in, const int* in_sizes, int n_in,
                              void* d_out, int out_size) {
    const float* x1 = (const float*)d_in[0];
    const float* x2 = (const float*)d_in[1];
    const int* ei1 = (const int*)d_in[2];
    const int* ei2 = (const int*)d_in[3];
    const float* Wk[2] = {(const float*)d_in[4], (const float*)d_in[13]};
    const float* bk[2] = {(const float*)d_in[5], (const float*)d_in[14]};
    const float* Wq[2] = {(const float*)d_in[6], (const float*)d_in[15]};
    const float* bq[2] = {(const float*)d_in[7], (const float*)d_in[16]};
    const float* Wv[2] = {(const float*)d_in[8], (const float*)d_in[17]};
    const float* bv[2] = {(const float*)d_in[9], (const float*)d_in[18]};
    const float* Wl[2] = {(const float*)d_in[10], (const float*)d_in[19]};
    const float* bl[2] = {(const float*)d_in[11], (const float*)d_in[20]};
    const float* Wr[2] = {(const float*)d_in[12], (const float*)d_in[21]};
    float* out = (float*)d_out;

    float *pX, *pK, *pV, *pQ, *pO, *pF, *pAGG, *pMEAN, *pDEG;
    cudaGetSymbolAddress((void**)&pX, g_X);
    cudaGetSymbolAddress((void**)&pK, g_Kb);
    cudaGetSymbolAddress((void**)&pV, g_Vb);
    cudaGetSymbolAddress((void**)&pQ, g_Qb);
    cudaGetSymbolAddress((void**)&pO, g_Ob);
    cudaGetSymbolAddress((void**)&pF, g_F);
    cudaGetSymbolAddress((void**)&pAGG, g_AGG);
    cudaGetSymbolAddress((void**)&pMEAN, g_MEAN);
    cudaGetSymbolAddress((void**)&pDEG, g_DEG);

    cudaFuncSetAttribute(flash_attn, cudaFuncAttributeMaxDynamicSharedMemorySize,
                         FLASH_SMEM);

    concat_x<<<(TN2 * DIM + 255) / 256, 256>>>(x1, x2, pX);
    zero_f<<<(TN2 + 255) / 256, 256>>>(pDEG, TN2);
    deg_count<<<(NEDGE + 255) / 256, 256>>>(ei1, 0, pDEG);
    deg_count<<<(NEDGE + 255) / 256, 256>>>(ei2, NNODES, pDEG);

    for (int L = 0; L < 2; L++) {
        gemm_n128<<<TN2 / 64, 256>>>(pX, Wk[L], bk[L], pK, 128, 0);
        gemm_n128<<<TN2 / 64, 256>>>(pX, Wv[L], bv[L], pV, 128, 0);
        gemm_n128<<<TN2 / 64, 256>>>(pX, Wq[L], bq[L], pQ, 128, 0);
        flash_attn<<<TN2 / 64, 256, FLASH_SMEM>>>(pQ, pK, pV, pO);
        build_feats<<<(TN2 * DIM + 255) / 256, 256>>>(pX, pO, pF);
        zero_f<<<(TN2 * FDIM + 255) / 256, 256>>>(pAGG, TN2 * FDIM);
        scatter_add<<<NEDGE, FDIM>>>(pF, ei1, 0, pAGG);
        scatter_add<<<NEDGE, FDIM>>>(pF, ei2, NNODES, pAGG);
        mean_div<<<(TN2 * FDIM + 255) / 256, 256>>>(pAGG, pDEG, pMEAN);
        gemm_n128<<<TN2 / 64, 256>>>(pMEAN, Wl[L], bl[L], pX, 256, 0);
        gemm_n128<<<TN2 / 64, 256>>>(pF, Wr[L], nullptr, pX, 256,
                                     FL_ACC | (L == 0 ? FL_RELU : 0));
    }

    dim3 grid(TN2 / 64, TN2 / 128);
    gemm_nt_sigmoid<<<grid, 256>>>(pX, out);
}

// round 6
// speedup vs baseline: 1.7704x; 1.7704x over previous
#include <cuda_runtime.h>
#include <cuda_bf16.h>
#include <mma.h>
#include <cstdint>
#include <math.h>

using namespace nvcuda;

#define NNODES 4096
#define TN2    8192
#define DIM    128
#define FDIM   256
#define NEDGE  65536

// ================= helpers (no inline asm anywhere in this file) =================
__device__ __forceinline__ __nv_bfloat16 bfhi(float v) { return __float2bfloat16(v); }
__device__ __forceinline__ __nv_bfloat16 bflo(float v) {
    return __float2bfloat16(v - __bfloat162float(__float2bfloat16(v)));
}

// ================= scratch (device globals; no allocation) =================
__device__ float g_X[TN2 * DIM];
__device__ float g_Kb[TN2 * DIM];
__device__ float g_Vb[TN2 * DIM];
__device__ float g_Qb[TN2 * DIM];
__device__ float g_F[TN2 * FDIM];
__device__ float g_AGG[TN2 * FDIM];
__device__ float g_MEAN[TN2 * FDIM];
__device__ float g_DEG[TN2];
__device__ float g_L[TN2];            // exp row sums
__device__ float g_OP[2 * TN2 * DIM]; // PV partials (2 key-halves)
__device__ __nv_bfloat16 g_Qhi[TN2 * DIM], g_Qlo[TN2 * DIM];
__device__ __nv_bfloat16 g_Khi[TN2 * DIM], g_Klo[TN2 * DIM];
__device__ __nv_bfloat16 g_Vthi[DIM * TN2], g_Vtlo[DIM * TN2]; // V transposed
__device__ __nv_bfloat16 g_Fhi[TN2 * DIM], g_Flo[TN2 * DIM];

// ================= small elementwise kernels =================
__global__ void concat_x(const float* __restrict__ x1, const float* __restrict__ x2,
                         float* __restrict__ X) {
    int i = blockIdx.x * blockDim.x + threadIdx.x;
    if (i < TN2 * DIM) X[i] = (i < NNODES * DIM) ? x1[i] : x2[i - NNODES * DIM];
}
__global__ void zero_f(float* __restrict__ p, int n) {
    int i = blockIdx.x * blockDim.x + threadIdx.x;
    if (i < n) p[i] = 0.f;
}
__global__ void deg_count(const int* __restrict__ ei, int off, float* __restrict__ deg) {
    int e = blockIdx.x * blockDim.x + threadIdx.x;
    if (e < NEDGE) atomicAdd(&deg[ei[NEDGE + e] + off], 1.0f);
}
__global__ void scatter_add(const float* __restrict__ feats, const int* __restrict__ ei,
                            int off, float* __restrict__ agg) {
    int e = blockIdx.x;
    int src = ei[e] + off;
    int dst = ei[NEDGE + e] + off;
    atomicAdd(&agg[dst * FDIM + threadIdx.x], feats[src * FDIM + threadIdx.x]);
}
__global__ void mean_div(const float* __restrict__ agg, const float* __restrict__ deg,
                         float* __restrict__ mean) {
    int i = blockIdx.x * blockDim.x + threadIdx.x;
    if (i < TN2 * FDIM) mean[i] = agg[i] / fmaxf(deg[i >> 8], 1.0f);
}
__global__ void build_feats2(const float* __restrict__ X, const float* __restrict__ OP,
                             const float* __restrict__ l, float* __restrict__ F) {
    int i = blockIdx.x * blockDim.x + threadIdx.x;
    if (i < TN2 * DIM) {
        int row = i >> 7, c = i & 127;
        float x = X[i];
        float o = (OP[i] + OP[TN2 * DIM + i]) / l[row];
        F[row * FDIM + c] = x;
        F[row * FDIM + DIM + c] = x - o;
    }
}
__global__ void split_bf16(const float* __restrict__ in, __nv_bfloat16* __restrict__ hi,
                           __nv_bfloat16* __restrict__ lo, float mult) {
    int i = blockIdx.x * blockDim.x + threadIdx.x;
    if (i < TN2 * DIM) {
        float v = in[i] * mult;
        hi[i] = bfhi(v);
        lo[i] = bflo(v);
    }
}
// V [8192,128] fp32 -> Vt hi/lo [128,8192] bf16 (64-key tiles)
__global__ void vt_split(const float* __restrict__ V, __nv_bfloat16* __restrict__ Vthi,
                         __nv_bfloat16* __restrict__ Vtlo) {
    __shared__ float t[64][132];
    int tid = threadIdx.x;
    int k0 = blockIdx.x * 64;
#pragma unroll
    for (int rep = 0; rep < 8; rep++) {
        int idx = rep * 256 + tid;
        int r = idx >> 5, c4 = (idx & 31) * 4;
        float4 v = *(const float4*)&V[(k0 + r) * DIM + c4];
        t[r][c4] = v.x; t[r][c4 + 1] = v.y; t[r][c4 + 2] = v.z; t[r][c4 + 3] = v.w;
    }
    __syncthreads();
    int d = tid >> 1, half = tid & 1;
    size_t base = (size_t)d * TN2 + k0 + half * 32;
#pragma unroll
    for (int j = 0; j < 32; j++) {
        float v = t[half * 32 + j][d];
        Vthi[base + j] = bfhi(v);
        Vtlo[base + j] = bflo(v);
    }
}

// ============ fp32 SIMT GEMM for small linears: C[M,128]=A[M,K]@B[K,128] ============
#define FL_RELU 1
#define FL_ACC  2
__global__ void gemm_n128(const float* __restrict__ A, const float* __restrict__ B,
                          const float* __restrict__ bias, float* __restrict__ C,
                          int K, int flags) {
    __shared__ float As[16 * 65];
    __shared__ float Bs[16 * 128];
    int tid = threadIdx.x;
    int tx = tid & 15, ty = tid >> 4;
    int m0 = blockIdx.x * 64;
    int arow = tid >> 2, akq = tid & 3;
    int brow = tid >> 5, bcol = (tid & 31) * 4;
    float acc[4][8];
#pragma unroll
    for (int i = 0; i < 4; i++)
#pragma unroll
        for (int j = 0; j < 8; j++) acc[i][j] = 0.f;
    for (int kt = 0; kt < K; kt += 16) {
        float4 av = *(const float4*)&A[(m0 + arow) * K + kt + akq * 4];
        As[(akq * 4 + 0) * 65 + arow] = av.x;
        As[(akq * 4 + 1) * 65 + arow] = av.y;
        As[(akq * 4 + 2) * 65 + arow] = av.z;
        As[(akq * 4 + 3) * 65 + arow] = av.w;
        *(float4*)&Bs[brow * 128 + bcol] = *(const float4*)&B[(kt + brow) * 128 + bcol];
        *(float4*)&Bs[(brow + 8) * 128 + bcol] = *(const float4*)&B[(kt + brow + 8) * 128 + bcol];
        __syncthreads();
#pragma unroll
        for (int kk = 0; kk < 16; kk++) {
            float a[4], b[8];
#pragma unroll
            for (int i = 0; i < 4; i++) a[i] = As[kk * 65 + ty + 16 * i];
#pragma unroll
            for (int j = 0; j < 8; j++) b[j] = Bs[kk * 128 + tx + 16 * j];
#pragma unroll
            for (int i = 0; i < 4; i++)
#pragma unroll
                for (int j = 0; j < 8; j++) acc[i][j] += a[i] * b[j];
        }
        __syncthreads();
    }
#pragma unroll
    for (int i = 0; i < 4; i++)
#pragma unroll
        for (int j = 0; j < 8; j++) {
            float v = acc[i][j];
            if (bias) v += bias[tx + 16 * j];
            int idx = (m0 + ty + 16 * i) * 128 + tx + 16 * j;
            if (flags & FL_ACC) v += C[idx];
            if (flags & FL_RELU) v = fmaxf(v, 0.f);
            C[idx] = v;
        }
}

// ======== fused flash attention via WMMA (no P materialization, no inline asm) ====
// grid (64 q-blocks, 2 key-halves), 256 threads = 8 warps, warp owns 16 query rows.
#define QSTR 136
#define VSTR 72
#define SQ   (128 * QSTR)          // halves per Q tile
#define SK   (64 * QSTR)
#define SV   (128 * VSTR)
#define OFF_QH 0
#define OFF_QL (OFF_QH + SQ)
#define OFF_KH (OFF_QL + SQ)
#define OFF_KL (OFF_KH + SK)
#define OFF_VH (OFF_KL + SK)
#define OFF_VL (OFF_VH + SV)
#define BF_HALVES (OFF_VL + SV)                 // 70656 halves = 141312 B
#define S_BYTES   (8 * 16 * 68 * 4)             // 34816 B
#define P_HALVES  (8 * 16 * 72)                 // per buffer
#define FL_SMEM   (BF_HALVES * 2 + S_BYTES + 2 * P_HALVES * 2)   // 212992 B

__global__ __launch_bounds__(256, 1) void flash_wmma(
    const __nv_bfloat16* __restrict__ Qhi, const __nv_bfloat16* __restrict__ Qlo,
    const __nv_bfloat16* __restrict__ Khi, const __nv_bfloat16* __restrict__ Klo,
    const __nv_bfloat16* __restrict__ Vthi, const __nv_bfloat16* __restrict__ Vtlo,
    float* __restrict__ OP, float* __restrict__ lsum) {
    extern __shared__ char smc[];
    __nv_bfloat16* sb = (__nv_bfloat16*)smc;
    float* sS = (float*)(smc + BF_HALVES * 2);
    __nv_bfloat16* sPh = (__nv_bfloat16*)(smc + BF_HALVES * 2 + S_BYTES);
    __nv_bfloat16* sPl = sPh + P_HALVES;

    int tid = threadIdx.x, lane = tid & 31, w = tid >> 5;
    int m0 = blockIdx.x * 128;
    int kh = blockIdx.y;
    int kbase = kh * (TN2 / 2);

    // stage Q hi/lo [128 x 128] (stride 136)
#pragma unroll
    for (int rep = 0; rep < 8; rep++) {
        int u = rep * 256 + tid;
        int row = u >> 4, c8 = (u & 15) * 8;
        *(uint4*)&sb[OFF_QH + row * QSTR + c8] =
            *(const uint4*)&Qhi[(size_t)(m0 + row) * DIM + c8];
        *(uint4*)&sb[OFF_QL + row * QSTR + c8] =
            *(const uint4*)&Qlo[(size_t)(m0 + row) * DIM + c8];
    }

    wmma::fragment<wmma::accumulator, 16, 16, 16, float> oacc[8];
#pragma unroll
    for (int n = 0; n < 8; n++) wmma::fill_fragment(oacc[n], 0.f);
    float rs = 0.f;
    float* mS = sS + w * 16 * 68;
    __nv_bfloat16* mPh = sPh + w * 16 * 72;
    __nv_bfloat16* mPl = sPl + w * 16 * 72;

    for (int c = 0; c < 64; c++) {
        int kc = kbase + c * 64;
        __syncthreads();
        // stage K hi/lo [64 keys x 128 dims]
#pragma unroll
        for (int rep = 0; rep < 4; rep++) {
            int u = rep * 256 + tid;
            int row = u >> 4, c8 = (u & 15) * 8;
            *(uint4*)&sb[OFF_KH + row * QSTR + c8] =
                *(const uint4*)&Khi[(size_t)(kc + row) * DIM + c8];
            *(uint4*)&sb[OFF_KL + row * QSTR + c8] =
                *(const uint4*)&Klo[(size_t)(kc + row) * DIM + c8];
        }
        // stage Vt hi/lo [128 dims x 64 keys]
#pragma unroll
        for (int rep = 0; rep < 4; rep++) {
            int u = rep * 256 + tid;
            int row = u >> 3, c8 = (u & 7) * 8;
            *(uint4*)&sb[OFF_VH + row * VSTR + c8] =
                *(const uint4*)&Vthi[(size_t)row * TN2 + kc + c8];
            *(uint4*)&sb[OFF_VL + row * VSTR + c8] =
                *(const uint4*)&Vtlo[(size_t)row * TN2 + kc + c8];
        }
        __syncthreads();

        // S[16x64] = Q_w K^T (3-term split)
        wmma::fragment<wmma::accumulator, 16, 16, 16, float> sfrag[4];
#pragma unroll
        for (int n = 0; n < 4; n++) wmma::fill_fragment(sfrag[n], 0.f);
#pragma unroll
        for (int ks = 0; ks < 8; ks++) {
            wmma::fragment<wmma::matrix_a, 16, 16, 16, __nv_bfloat16, wmma::row_major> ah, al;
            wmma::load_matrix_sync(ah, sb + OFF_QH + (w * 16) * QSTR + ks * 16, QSTR);
            wmma::load_matrix_sync(al, sb + OFF_QL + (w * 16) * QSTR + ks * 16, QSTR);
#pragma unroll
            for (int n = 0; n < 4; n++) {
                wmma::fragment<wmma::matrix_b, 16, 16, 16, __nv_bfloat16, wmma::col_major> bh, bl;
                wmma::load_matrix_sync(bh, sb + OFF_KH + (n * 16) * QSTR + ks * 16, QSTR);
                wmma::load_matrix_sync(bl, sb + OFF_KL + (n * 16) * QSTR + ks * 16, QSTR);
                wmma::mma_sync(sfrag[n], ah, bh, sfrag[n]);
                wmma::mma_sync(sfrag[n], ah, bl, sfrag[n]);
                wmma::mma_sync(sfrag[n], al, bh, sfrag[n]);
            }
        }
#pragma unroll
        for (int n = 0; n < 4; n++)
            wmma::store_matrix_sync(mS + n * 16, sfrag[n], 68, wmma::mem_row_major);
        __syncwarp();

        // scalar pass: exp + row-sum + bf16 hi/lo split (warp-private region)
        {
            int r = lane >> 1, c0 = (lane & 1) * 32;
#pragma unroll
            for (int j = 0; j < 32; j++) {
                float e = __expf(mS[r * 68 + c0 + j]);
                rs += e;
                mPh[r * 72 + c0 + j] = bfhi(e);
                mPl[r * 72 + c0 + j] = bflo(e);
            }
        }
        __syncwarp();

        // O += P V (3-term split)
#pragma unroll
        for (int kt = 0; kt < 4; kt++) {
            wmma::fragment<wmma::matrix_a, 16, 16, 16, __nv_bfloat16, wmma::row_major> pah, pal;
            wmma::load_matrix_sync(pah, mPh + kt * 16, 72);
            wmma::load_matrix_sync(pal, mPl + kt * 16, 72);
#pragma unroll
            for (int n = 0; n < 8; n++) {
                wmma::fragment<wmma::matrix_b, 16, 16, 16, __nv_bfloat16, wmma::col_major> vh, vl;
                wmma::load_matrix_sync(vh, sb + OFF_VH + (n * 16) * VSTR + kt * 16, VSTR);
                wmma::load_matrix_sync(vl, sb + OFF_VL + (n * 16) * VSTR + kt * 16, VSTR);
                wmma::mma_sync(oacc[n], pah, vh, oacc[n]);
                wmma::mma_sync(oacc[n], pah, vl, oacc[n]);
                wmma::mma_sync(oacc[n], pal, vh, oacc[n]);
            }
        }
    }

    // store O partial + row sums
    float* dst = OP + (size_t)kh * TN2 * DIM + (size_t)(m0 + w * 16) * DIM;
#pragma unroll
    for (int n = 0; n < 8; n++)
        wmma::store_matrix_sync(dst + n * 16, oacc[n], DIM, wmma::mem_row_major);
    rs += __shfl_xor_sync(0xffffffffu, rs, 1);
    if ((lane & 1) == 0) atomicAdd(&lsum[m0 + w * 16 + (lane >> 1)], rs);
}

// ======== WMMA NT GEMM + sigmoid: out[8192,8192] = sigmoid(F F^T), K=128 ========
#define SSTR 72
#define ADJ_TILE (128 * SSTR)
#define ADJ_SMEM (4 * ADJ_TILE * 2)    // 73728 B

__global__ __launch_bounds__(256, 1) void adj_sigmoid(
    const __nv_bfloat16* __restrict__ Ahi, const __nv_bfloat16* __restrict__ Alo,
    float* __restrict__ outF) {
    extern __shared__ __nv_bfloat16 smb[];
    int tid = threadIdx.x, w = tid >> 5;
    int wm = (w & 3) * 32, wn = (w >> 2) * 64;
    int m0 = blockIdx.x * 128, n0 = blockIdx.y * 128;
    __nv_bfloat16* sAh = smb;
    __nv_bfloat16* sAl = smb + ADJ_TILE;
    __nv_bfloat16* sBh = smb + 2 * ADJ_TILE;
    __nv_bfloat16* sBl = smb + 3 * ADJ_TILE;

    wmma::fragment<wmma::accumulator, 16, 16, 16, float> acc[2][4];
#pragma unroll
    for (int mt = 0; mt < 2; mt++)
#pragma unroll
        for (int nt = 0; nt < 4; nt++) wmma::fill_fragment(acc[mt][nt], 0.f);

    for (int ch = 0; ch < 2; ch++) {
        int k0 = ch * 64;
        const __nv_bfloat16* srcs[4] = {Ahi, Alo, Ahi, Alo};
        __nv_bfloat16* dsts[4] = {sAh, sAl, sBh, sBl};
        const int rb[4] = {m0, m0, n0, n0};
#pragma unroll
        for (int m = 0; m < 4; m++) {
#pragma unroll
            for (int rep = 0; rep < 4; rep++) {
                int u = rep * 256 + tid;
                int row = u >> 3, c8 = (u & 7) * 8;
                *(uint4*)&dsts[m][row * SSTR + c8] =
                    *(const uint4*)&srcs[m][(size_t)(rb[m] + row) * DIM + k0 + c8];
            }
        }
        __syncthreads();
#pragma unroll
        for (int ks = 0; ks < 4; ks++) {
            wmma::fragment<wmma::matrix_a, 16, 16, 16, __nv_bfloat16, wmma::row_major> ah[2], al[2];
#pragma unroll
            for (int mt = 0; mt < 2; mt++) {
                wmma::load_matrix_sync(ah[mt], sAh + (wm + mt * 16) * SSTR + ks * 16, SSTR);
                wmma::load_matrix_sync(al[mt], sAl + (wm + mt * 16) * SSTR + ks * 16, SSTR);
            }
#pragma unroll
            for (int nt = 0; nt < 4; nt++) {
                wmma::fragment<wmma::matrix_b, 16, 16, 16, __nv_bfloat16, wmma::col_major> bh, bl;
                wmma::load_matrix_sync(bh, sBh + (wn + nt * 16) * SSTR + ks * 16, SSTR);
                wmma::load_matrix_sync(bl, sBl + (wn + nt * 16) * SSTR + ks * 16, SSTR);
#pragma unroll
                for (int mt = 0; mt < 2; mt++) {
                    wmma::mma_sync(acc[mt][nt], ah[mt], bh, acc[mt][nt]);
                    wmma::mma_sync(acc[mt][nt], ah[mt], bl, acc[mt][nt]);
                    wmma::mma_sync(acc[mt][nt], al[mt], bh, acc[mt][nt]);
                }
            }
        }
        __syncthreads();
    }

#pragma unroll
    for (int mt = 0; mt < 2; mt++)
#pragma unroll
        for (int nt = 0; nt < 4; nt++) {
#pragma unroll
            for (int i = 0; i < acc[mt][nt].num_elements; i++)
                acc[mt][nt].x[i] = 1.f / (1.f + __expf(-acc[mt][nt].x[i]));
            float* dst = outF + (size_t)(m0 + wm + mt * 16) * TN2 + n0 + wn + nt * 16;
            wmma::store_matrix_sync(dst, acc[mt][nt], TN2, wmma::mem_row_major);
        }
}

// ================= host orchestration =================
extern "C" void kernel_launch(void* const* d_in, const int* in_sizes, int n_in,
                              void* d_out, int out_size) {
    const float* x1 = (const float*)d_in[0];
    const float* x2 = (const float*)d_in[1];
    const int* ei1 = (const int*)d_in[2];
    const int* ei2 = (const int*)d_in[3];
    const float* Wk[2] = {(const float*)d_in[4], (const float*)d_in[13]};
    const float* bk[2] = {(const float*)d_in[5], (const float*)d_in[14]};
    const float* Wq[2] = {(const float*)d_in[6], (const float*)d_in[15]};
    const float* bq[2] = {(const float*)d_in[7], (const float*)d_in[16]};
    const float* Wv[2] = {(const float*)d_in[8], (const float*)d_in[17]};
    const float* bv[2] = {(const float*)d_in[9], (const float*)d_in[18]};
    const float* Wl[2] = {(const float*)d_in[10], (const float*)d_in[19]};
    const float* bl[2] = {(const float*)d_in[11], (const float*)d_in[20]};
    const float* Wr[2] = {(const float*)d_in[12], (const float*)d_in[21]};
    float* out = (float*)d_out;

    float *pX, *pK, *pV, *pQ, *pF, *pAGG, *pMEAN, *pDEG, *pL, *pOP;
    __nv_bfloat16 *pQh, *pQl, *pKh, *pKl, *pVth, *pVtl, *pFh, *pFl;
    cudaGetSymbolAddress((void**)&pX, g_X);
    cudaGetSymbolAddress((void**)&pK, g_Kb);
    cudaGetSymbolAddress((void**)&pV, g_Vb);
    cudaGetSymbolAddress((void**)&pQ, g_Qb);
    cudaGetSymbolAddress((void**)&pF, g_F);
    cudaGetSymbolAddress((void**)&pAGG, g_AGG);
    cudaGetSymbolAddress((void**)&pMEAN, g_MEAN);
    cudaGetSymbolAddress((void**)&pDEG, g_DEG);
    cudaGetSymbolAddress((void**)&pL, g_L);
    cudaGetSymbolAddress((void**)&pOP, g_OP);
    cudaGetSymbolAddress((void**)&pQh, g_Qhi);
    cudaGetSymbolAddress((void**)&pQl, g_Qlo);
    cudaGetSymbolAddress((void**)&pKh, g_Khi);
    cudaGetSymbolAddress((void**)&pKl, g_Klo);
    cudaGetSymbolAddress((void**)&pVth, g_Vthi);
    cudaGetSymbolAddress((void**)&pVtl, g_Vtlo);
    cudaGetSymbolAddress((void**)&pFh, g_Fhi);
    cudaGetSymbolAddress((void**)&pFl, g_Flo);

    cudaFuncSetAttribute(flash_wmma, cudaFuncAttributeMaxDynamicSharedMemorySize, FL_SMEM);
    cudaFuncSetAttribute(adj_sigmoid, cudaFuncAttributeMaxDynamicSharedMemorySize, ADJ_SMEM);

    const float isc = 0.08838834764831845f;  // 1/sqrt(128)
    const int EW = (TN2 * DIM + 255) / 256;

    concat_x<<<EW, 256>>>(x1, x2, pX);
    zero_f<<<(TN2 + 255) / 256, 256>>>(pDEG, TN2);
    deg_count<<<(NEDGE + 255) / 256, 256>>>(ei1, 0, pDEG);
    deg_count<<<(NEDGE + 255) / 256, 256>>>(ei2, NNODES, pDEG);

    for (int L = 0; L < 2; L++) {
        gemm_n128<<<TN2 / 64, 256>>>(pX, Wk[L], bk[L], pK, 128, 0);
        gemm_n128<<<TN2 / 64, 256>>>(pX, Wv[L], bv[L], pV, 128, 0);
        gemm_n128<<<TN2 / 64, 256>>>(pX, Wq[L], bq[L], pQ, 128, 0);
        split_bf16<<<EW, 256>>>(pQ, pQh, pQl, isc);
        split_bf16<<<EW, 256>>>(pK, pKh, pKl, 1.0f);
        vt_split<<<TN2 / 64, 256>>>(pV, pVth, pVtl);
        zero_f<<<(TN2 + 255) / 256, 256>>>(pL, TN2);
        dim3 gfl(TN2 / 128, 2);
        flash_wmma<<<gfl, 256, FL_SMEM>>>(pQh, pQl, pKh, pKl, pVth, pVtl, pOP, pL);
        build_feats2<<<EW, 256>>>(pX, pOP, pL, pF);
        zero_f<<<(TN2 * FDIM + 255) / 256, 256>>>(pAGG, TN2 * FDIM);
        scatter_add<<<NEDGE, FDIM>>>(pF, ei1, 0, pAGG);
        scatter_add<<<NEDGE, FDIM>>>(pF, ei2, NNODES, pAGG);
        mean_div<<<(TN2 * FDIM + 255) / 256, 256>>>(pAGG, pDEG, pMEAN);
        gemm_n128<<<TN2 / 64, 256>>>(pMEAN, Wl[L], bl[L], pX, 256, 0);
        gemm_n128<<<TN2 / 64, 256>>>(pF, Wr[L], nullptr, pX, 256,
                                     FL_ACC | (L == 0 ? FL_RELU : 0));
    }

    split_bf16<<<EW, 256>>>(pX, pFh, pFl, 1.0f);
    dim3 gf(TN2 / 128, TN2 / 128);
    adj_sigmoid<<<gf, 256, ADJ_SMEM>>>(pFh, pFl, out);
}

// round 8
// speedup vs baseline: 2.5571x; 1.4443x over previous
#include <cuda_runtime.h>
#include <cuda_fp16.h>
#include <mma.h>
#include <cstdint>
#include <math.h>

using namespace nvcuda;

#define NNODES 4096
#define TN2    8192
#define DIM    128
#define FDIM   256
#define NEDGE  65536

// ================= helpers (intrinsics only, no inline asm, no cp.async) =========
__device__ __forceinline__ __half f16hi(float v) { return __float2half(v); }
__device__ __forceinline__ __half f16lo(float v) {
    return __float2half(v - __half2float(__float2half(v)));
}

// ================= scratch (device globals; no allocation) =================
__device__ float g_X[TN2 * DIM];
__device__ float g_Kb[TN2 * DIM];
__device__ float g_Vb[TN2 * DIM];
__device__ float g_Qb[TN2 * DIM];
__device__ float g_F[TN2 * FDIM];
__device__ float g_AGG[TN2 * FDIM];
__device__ float g_MEAN[TN2 * FDIM];
__device__ float g_DEG[TN2];
__device__ float g_L[TN2];            // exp row sums
__device__ float g_OP[2 * TN2 * DIM]; // PV partials (2 key-halves)
__device__ __half g_Qh[TN2 * DIM];                      // fp16(Q * isc)
__device__ __half g_Kh[TN2 * DIM], g_Kl[TN2 * DIM];     // K split
__device__ __half g_Vth[DIM * TN2], g_Vtl[DIM * TN2];   // V^T split
__device__ __half g_Fh[TN2 * DIM], g_Fl[TN2 * DIM];     // final feats split

// ================= small elementwise kernels =================
__global__ void concat_x(const float* __restrict__ x1, const float* __restrict__ x2,
                         float* __restrict__ X) {
    int i = blockIdx.x * blockDim.x + threadIdx.x;
    if (i < TN2 * DIM) X[i] = (i < NNODES * DIM) ? x1[i] : x2[i - NNODES * DIM];
}
__global__ void zero_f(float* __restrict__ p, int n) {
    int i = blockIdx.x * blockDim.x + threadIdx.x;
    if (i < n) p[i] = 0.f;
}
__global__ void deg_count(const int* __restrict__ ei, int off, float* __restrict__ deg) {
    int e = blockIdx.x * blockDim.x + threadIdx.x;
    if (e < NEDGE) atomicAdd(&deg[ei[NEDGE + e] + off], 1.0f);
}
__global__ void scatter_add(const float* __restrict__ feats, const int* __restrict__ ei,
                            int off, float* __restrict__ agg) {
    int e = blockIdx.x;
    int src = ei[e] + off;
    int dst = ei[NEDGE + e] + off;
    atomicAdd(&agg[dst * FDIM + threadIdx.x], feats[src * FDIM + threadIdx.x]);
}
__global__ void mean_div(const float* __restrict__ agg, const float* __restrict__ deg,
                         float* __restrict__ mean) {
    int i = blockIdx.x * blockDim.x + threadIdx.x;
    if (i < TN2 * FDIM) mean[i] = agg[i] / fmaxf(deg[i >> 8], 1.0f);
}
__global__ void build_feats2(const float* __restrict__ X, const float* __restrict__ OP,
                             const float* __restrict__ l, float* __restrict__ F) {
    int i = blockIdx.x * blockDim.x + threadIdx.x;
    if (i < TN2 * DIM) {
        int row = i >> 7, c = i & 127;
        float x = X[i];
        float o = (OP[i] + OP[TN2 * DIM + i]) / l[row];
        F[row * FDIM + c] = x;
        F[row * FDIM + DIM + c] = x - o;
    }
}
__global__ void round_f16(const float* __restrict__ in, __half* __restrict__ hi,
                          float mult) {
    int i = blockIdx.x * blockDim.x + threadIdx.x;
    if (i < TN2 * DIM) hi[i] = f16hi(in[i] * mult);
}
__global__ void split_f16(const float* __restrict__ in, __half* __restrict__ hi,
                          __half* __restrict__ lo) {
    int i = blockIdx.x * blockDim.x + threadIdx.x;
    if (i < TN2 * DIM) {
        float v = in[i];
        hi[i] = f16hi(v);
        lo[i] = f16lo(v);
    }
}
// V [8192,128] fp32 -> Vt hi/lo [128,8192] fp16 (64-key tiles)
__global__ void vt_split_f16(const float* __restrict__ V, __half* __restrict__ Vth,
                             __half* __restrict__ Vtl) {
    __shared__ float t[64][132];
    int tid = threadIdx.x;
    int k0 = blockIdx.x * 64;
#pragma unroll
    for (int rep = 0; rep < 8; rep++) {
        int idx = rep * 256 + tid;
        int r = idx >> 5, c4 = (idx & 31) * 4;
        float4 v = *(const float4*)&V[(k0 + r) * DIM + c4];
        t[r][c4] = v.x; t[r][c4 + 1] = v.y; t[r][c4 + 2] = v.z; t[r][c4 + 3] = v.w;
    }
    __syncthreads();
    int d = tid >> 1, half_ = tid & 1;
    size_t base = (size_t)d * TN2 + k0 + half_ * 32;
#pragma unroll
    for (int j = 0; j < 32; j++) {
        float v = t[half_ * 32 + j][d];
        Vth[base + j] = f16hi(v);
        Vtl[base + j] = f16lo(v);
    }
}

// ============ fp32 SIMT GEMM for small linears: C[M,128]=A[M,K]@B[K,128] ============
#define FL_RELU 1
#define FL_ACC  2
__global__ void gemm_n128(const float* __restrict__ A, const float* __restrict__ B,
                          const float* __restrict__ bias, float* __restrict__ C,
                          int K, int flags) {
    __shared__ float As[16 * 65];
    __shared__ float Bs[16 * 128];
    int tid = threadIdx.x;
    int tx = tid & 15, ty = tid >> 4;
    int m0 = blockIdx.x * 64;
    int arow = tid >> 2, akq = tid & 3;
    int brow = tid >> 5, bcol = (tid & 31) * 4;
    float acc[4][8];
#pragma unroll
    for (int i = 0; i < 4; i++)
#pragma unroll
        for (int j = 0; j < 8; j++) acc[i][j] = 0.f;
    for (int kt = 0; kt < K; kt += 16) {
        float4 av = *(const float4*)&A[(m0 + arow) * K + kt + akq * 4];
        As[(akq * 4 + 0) * 65 + arow] = av.x;
        As[(akq * 4 + 1) * 65 + arow] = av.y;
        As[(akq * 4 + 2) * 65 + arow] = av.z;
        As[(akq * 4 + 3) * 65 + arow] = av.w;
        *(float4*)&Bs[brow * 128 + bcol] = *(const float4*)&B[(kt + brow) * 128 + bcol];
        *(float4*)&Bs[(brow + 8) * 128 + bcol] = *(const float4*)&B[(kt + brow + 8) * 128 + bcol];
        __syncthreads();
#pragma unroll
        for (int kk = 0; kk < 16; kk++) {
            float a[4], b[8];
#pragma unroll
            for (int i = 0; i < 4; i++) a[i] = As[kk * 65 + ty + 16 * i];
#pragma unroll
            for (int j = 0; j < 8; j++) b[j] = Bs[kk * 128 + tx + 16 * j];
#pragma unroll
            for (int i = 0; i < 4; i++)
#pragma unroll
                for (int j = 0; j < 8; j++) acc[i][j] += a[i] * b[j];
        }
        __syncthreads();
    }
#pragma unroll
    for (int i = 0; i < 4; i++)
#pragma unroll
        for (int j = 0; j < 8; j++) {
            float v = acc[i][j];
            if (bias) v += bias[tx + 16 * j];
            int idx = (m0 + ty + 16 * i) * 128 + tx + 16 * j;
            if (flags & FL_ACC) v += C[idx];
            if (flags & FL_RELU) v = fmaxf(v, 0.f);
            C[idx] = v;
        }
}

// ======== fused flash attention: fp16 2-term, single-buffered (R6-proven staging) ====
// grid (64 q-blocks, 2 key-halves), 256 threads = 8 warps, warp owns 16 query rows.
#define QSTR 136
#define VSTR 72
#define OFF_Q  0
#define OFF_KH (OFF_Q + 128 * QSTR)
#define OFF_KL (OFF_KH + 64 * QSTR)
#define OFF_VH (OFF_KL + 64 * QSTR)
#define OFF_VL (OFF_VH + 128 * VSTR)
#define HB     ((OFF_VL + 128 * VSTR) * 2)   // 106496 B
#define SB     (8 * 16 * 68 * 4)             // 34816 B
#define PB     (8 * 16 * 72 * 2)             // 18432 B
#define FL_SMEM (HB + SB + PB)               // 159744 B

__global__ __launch_bounds__(256, 1) void flash_f16(
    const __half* __restrict__ Qh, const __half* __restrict__ Kh,
    const __half* __restrict__ Kl, const __half* __restrict__ Vth,
    const __half* __restrict__ Vtl, float* __restrict__ OP,
    float* __restrict__ lsum) {
    extern __shared__ char smc[];
    __half* sb = (__half*)smc;
    float* sS = (float*)(smc + HB);
    __half* sP = (__half*)(smc + HB + SB);

    int tid = threadIdx.x, lane = tid & 31, w = tid >> 5;
    int m0 = blockIdx.x * 128;
    int kh = blockIdx.y;
    int kbase = kh * (TN2 / 2);

    // stage Q_hi [128 x 128]
#pragma unroll
    for (int rep = 0; rep < 8; rep++) {
        int u = rep * 256 + tid;
        int row = u >> 4, c8 = (u & 15) * 8;
        *(uint4*)&sb[OFF_Q + row * QSTR + c8] =
            *(const uint4*)&Qh[(size_t)(m0 + row) * DIM + c8];
    }

    wmma::fragment<wmma::accumulator, 16, 16, 16, float> oacc[8];
#pragma unroll
    for (int n = 0; n < 8; n++) wmma::fill_fragment(oacc[n], 0.f);
    float rs = 0.f;
    float* mS = sS + w * (16 * 68);
    __half* mP = sP + w * (16 * 72);

    for (int c = 0; c < 64; c++) {
        int kc = kbase + c * 64;
        __syncthreads();
        // stage K hi/lo [64 keys x 128 dims]
#pragma unroll
        for (int rep = 0; rep < 4; rep++) {
            int u = rep * 256 + tid;
            int row = u >> 4, c8 = (u & 15) * 8;
            *(uint4*)&sb[OFF_KH + row * QSTR + c8] =
                *(const uint4*)&Kh[(size_t)(kc + row) * DIM + c8];
            *(uint4*)&sb[OFF_KL + row * QSTR + c8] =
                *(const uint4*)&Kl[(size_t)(kc + row) * DIM + c8];
        }
        // stage Vt hi/lo [128 dims x 64 keys]
#pragma unroll
        for (int rep = 0; rep < 4; rep++) {
            int u = rep * 256 + tid;
            int row = u >> 3, c8 = (u & 7) * 8;
            *(uint4*)&sb[OFF_VH + row * VSTR + c8] =
                *(const uint4*)&Vth[(size_t)row * TN2 + kc + c8];
            *(uint4*)&sb[OFF_VL + row * VSTR + c8] =
                *(const uint4*)&Vtl[(size_t)row * TN2 + kc + c8];
        }
        __syncthreads();

        // S[16x64] = Q_w K^T (2-term: Qh*Kh + Qh*Kl)
        wmma::fragment<wmma::accumulator, 16, 16, 16, float> sf[4];
#pragma unroll
        for (int n = 0; n < 4; n++) wmma::fill_fragment(sf[n], 0.f);
#pragma unroll
        for (int ks = 0; ks < 8; ks++) {
            wmma::fragment<wmma::matrix_a, 16, 16, 16, __half, wmma::row_major> a;
            wmma::load_matrix_sync(a, sb + OFF_Q + (w * 16) * QSTR + ks * 16, QSTR);
#pragma unroll
            for (int n = 0; n < 4; n++) {
                wmma::fragment<wmma::matrix_b, 16, 16, 16, __half, wmma::col_major> bh, bl;
                wmma::load_matrix_sync(bh, sb + OFF_KH + (n * 16) * QSTR + ks * 16, QSTR);
                wmma::load_matrix_sync(bl, sb + OFF_KL + (n * 16) * QSTR + ks * 16, QSTR);
                wmma::mma_sync(sf[n], a, bh, sf[n]);
                wmma::mma_sync(sf[n], a, bl, sf[n]);
            }
        }
#pragma unroll
        for (int n = 0; n < 4; n++)
            wmma::store_matrix_sync(mS + n * 16, sf[n], 68, wmma::mem_row_major);
        __syncwarp();

        // scalar: exp + rowsum + fp16 round (warp-private regions)
        {
            int r = lane >> 1, c0 = (lane & 1) * 32;
            float rsl = 0.f;
#pragma unroll
            for (int j = 0; j < 32; j++) {
                float e = __expf(mS[r * 68 + c0 + j]);
                rsl += e;
                mP[r * 72 + c0 + j] = __float2half(e);
            }
            rs += rsl;
        }
        __syncwarp();

        // O += P V (2-term: P*Vh + P*Vl)
#pragma unroll
        for (int kt = 0; kt < 4; kt++) {
            wmma::fragment<wmma::matrix_a, 16, 16, 16, __half, wmma::row_major> pa;
            wmma::load_matrix_sync(pa, mP + kt * 16, 72);
#pragma unroll
            for (int n = 0; n < 8; n++) {
                wmma::fragment<wmma::matrix_b, 16, 16, 16, __half, wmma::col_major> vh, vl;
                wmma::load_matrix_sync(vh, sb + OFF_VH + (n * 16) * VSTR + kt * 16, VSTR);
                wmma::load_matrix_sync(vl, sb + OFF_VL + (n * 16) * VSTR + kt * 16, VSTR);
                wmma::mma_sync(oacc[n], pa, vh, oacc[n]);
                wmma::mma_sync(oacc[n], pa, vl, oacc[n]);
            }
        }
    }

    // store O partial + row sums
    float* dst = OP + (size_t)kh * TN2 * DIM + (size_t)(m0 + w * 16) * DIM;
#pragma unroll
    for (int n = 0; n < 8; n++)
        wmma::store_matrix_sync(dst + n * 16, oacc[n], DIM, wmma::mem_row_major);
    rs += __shfl_xor_sync(0xffffffffu, rs, 1);
    if ((lane & 1) == 0) atomicAdd(&lsum[m0 + w * 16 + (lane >> 1)], rs);
}

// ======== fp16 2-term NT GEMM + sigmoid: out = sigmoid(F F^T), K=128 staged whole ====
#define ASTR 136
#define ADJ_TILE (128 * ASTR)
#define ADJ_SMEM (3 * ADJ_TILE * 2)   // 104448 B -> 2 CTAs/SM

__global__ __launch_bounds__(256, 2) void adj_sigmoid(
    const __half* __restrict__ Fh, const __half* __restrict__ Fl,
    float* __restrict__ outF) {
    extern __shared__ __half smb[];
    int tid = threadIdx.x, w = tid >> 5;
    int wm = (w & 3) * 32, wn = (w >> 2) * 64;
    int m0 = blockIdx.x * 128, n0 = blockIdx.y * 128;
    __half* sA = smb;                    // F_hi rows m0 (A side, rounded)
    __half* sBh = smb + ADJ_TILE;        // F_hi rows n0
    __half* sBl = smb + 2 * ADJ_TILE;    // F_lo rows n0

#pragma unroll
    for (int rep = 0; rep < 8; rep++) {
        int u = rep * 256 + tid;
        int row = u >> 4, c8 = (u & 15) * 8;
        *(uint4*)&sA[row * ASTR + c8] = *(const uint4*)&Fh[(size_t)(m0 + row) * DIM + c8];
        *(uint4*)&sBh[row * ASTR + c8] = *(const uint4*)&Fh[(size_t)(n0 + row) * DIM + c8];
        *(uint4*)&sBl[row * ASTR + c8] = *(const uint4*)&Fl[(size_t)(n0 + row) * DIM + c8];
    }
    __syncthreads();

    wmma::fragment<wmma::accumulator, 16, 16, 16, float> acc[2][4];
#pragma unroll
    for (int mt = 0; mt < 2; mt++)
#pragma unroll
        for (int nt = 0; nt < 4; nt++) wmma::fill_fragment(acc[mt][nt], 0.f);

#pragma unroll
    for (int ks = 0; ks < 8; ks++) {
        wmma::fragment<wmma::matrix_a, 16, 16, 16, __half, wmma::row_major> a[2];
#pragma unroll
        for (int mt = 0; mt < 2; mt++)
            wmma::load_matrix_sync(a[mt], sA + (wm + mt * 16) * ASTR + ks * 16, ASTR);
#pragma unroll
        for (int nt = 0; nt < 4; nt++) {
            wmma::fragment<wmma::matrix_b, 16, 16, 16, __half, wmma::col_major> bh, bl;
            wmma::load_matrix_sync(bh, sBh + (wn + nt * 16) * ASTR + ks * 16, ASTR);
            wmma::load_matrix_sync(bl, sBl + (wn + nt * 16) * ASTR + ks * 16, ASTR);
#pragma unroll
            for (int mt = 0; mt < 2; mt++) {
                wmma::mma_sync(acc[mt][nt], a[mt], bh, acc[mt][nt]);
                wmma::mma_sync(acc[mt][nt], a[mt], bl, acc[mt][nt]);
            }
        }
    }

#pragma unroll
    for (int mt = 0; mt < 2; mt++)
#pragma unroll
        for (int nt = 0; nt < 4; nt++) {
#pragma unroll
            for (int i = 0; i < acc[mt][nt].num_elements; i++)
                acc[mt][nt].x[i] = 1.f / (1.f + __expf(-acc[mt][nt].x[i]));
            float* dst = outF + (size_t)(m0 + wm + mt * 16) * TN2 + n0 + wn + nt * 16;
            wmma::store_matrix_sync(dst, acc[mt][nt], TN2, wmma::mem_row_major);
        }
}

// ================= host orchestration =================
extern "C" void kernel_launch(void* const* d_in, const int* in_sizes, int n_in,
                              void* d_out, int out_size) {
    const float* x1 = (const float*)d_in[0];
    const float* x2 = (const float*)d_in[1];
    const int* ei1 = (const int*)d_in[2];
    const int* ei2 = (const int*)d_in[3];
    const float* Wk[2] = {(const float*)d_in[4], (const float*)d_in[13]};
    const float* bk[2] = {(const float*)d_in[5], (const float*)d_in[14]};
    const float* Wq[2] = {(const float*)d_in[6], (const float*)d_in[15]};
    const float* bq[2] = {(const float*)d_in[7], (const float*)d_in[16]};
    const float* Wv[2] = {(const float*)d_in[8], (const float*)d_in[17]};
    const float* bv[2] = {(const float*)d_in[9], (const float*)d_in[18]};
    const float* Wl[2] = {(const float*)d_in[10], (const float*)d_in[19]};
    const float* bl[2] = {(const float*)d_in[11], (const float*)d_in[20]};
    const float* Wr[2] = {(const float*)d_in[12], (const float*)d_in[21]};
    float* out = (float*)d_out;

    float *pX, *pK, *pV, *pQ, *pF, *pAGG, *pMEAN, *pDEG, *pL, *pOP;
    __half *pQh, *pKh, *pKl, *pVth, *pVtl, *pFh, *pFl;
    cudaGetSymbolAddress((void**)&pX, g_X);
    cudaGetSymbolAddress((void**)&pK, g_Kb);
    cudaGetSymbolAddress((void**)&pV, g_Vb);
    cudaGetSymbolAddress((void**)&pQ, g_Qb);
    cudaGetSymbolAddress((void**)&pF, g_F);
    cudaGetSymbolAddress((void**)&pAGG, g_AGG);
    cudaGetSymbolAddress((void**)&pMEAN, g_MEAN);
    cudaGetSymbolAddress((void**)&pDEG, g_DEG);
    cudaGetSymbolAddress((void**)&pL, g_L);
    cudaGetSymbolAddress((void**)&pOP, g_OP);
    cudaGetSymbolAddress((void**)&pQh, g_Qh);
    cudaGetSymbolAddress((void**)&pKh, g_Kh);
    cudaGetSymbolAddress((void**)&pKl, g_Kl);
    cudaGetSymbolAddress((void**)&pVth, g_Vth);
    cudaGetSymbolAddress((void**)&pVtl, g_Vtl);
    cudaGetSymbolAddress((void**)&pFh, g_Fh);
    cudaGetSymbolAddress((void**)&pFl, g_Fl);

    cudaFuncSetAttribute(flash_f16, cudaFuncAttributeMaxDynamicSharedMemorySize, FL_SMEM);
    cudaFuncSetAttribute(adj_sigmoid, cudaFuncAttributeMaxDynamicSharedMemorySize, ADJ_SMEM);

    const float isc = 0.08838834764831845f;  // 1/sqrt(128)
    const int EW = (TN2 * DIM + 255) / 256;

    concat_x<<<EW, 256>>>(x1, x2, pX);
    zero_f<<<(TN2 + 255) / 256, 256>>>(pDEG, TN2);
    deg_count<<<(NEDGE + 255) / 256, 256>>>(ei1, 0, pDEG);
    deg_count<<<(NEDGE + 255) / 256, 256>>>(ei2, NNODES, pDEG);

    for (int L = 0; L < 2; L++) {
        gemm_n128<<<TN2 / 64, 256>>>(pX, Wk[L], bk[L], pK, 128, 0);
        gemm_n128<<<TN2 / 64, 256>>>(pX, Wv[L], bv[L], pV, 128, 0);
        gemm_n128<<<TN2 / 64, 256>>>(pX, Wq[L], bq[L], pQ, 128, 0);
        round_f16<<<EW, 256>>>(pQ, pQh, isc);
        split_f16<<<EW, 256>>>(pK, pKh, pKl);
        vt_split_f16<<<TN2 / 64, 256>>>(pV, pVth, pVtl);
        zero_f<<<(TN2 + 255) / 256, 256>>>(pL, TN2);
        dim3 gfl(TN2 / 128, 2);
        flash_f16<<<gfl, 256, FL_SMEM>>>(pQh, pKh, pKl, pVth, pVtl, pOP, pL);
        build_feats2<<<EW, 256>>>(pX, pOP, pL, pF);
        zero_f<<<(TN2 * FDIM + 255) / 256, 256>>>(pAGG, TN2 * FDIM);
        scatter_add<<<NEDGE, FDIM>>>(pF, ei1, 0, pAGG);
        scatter_add<<<NEDGE, FDIM>>>(pF, ei2, NNODES, pAGG);
        mean_div<<<(TN2 * FDIM + 255) / 256, 256>>>(pAGG, pDEG, pMEAN);
        gemm_n128<<<TN2 / 64, 256>>>(pMEAN, Wl[L], bl[L], pX, 256, 0);
        gemm_n128<<<TN2 / 64, 256>>>(pF, Wr[L], nullptr, pX, 256,
                                     FL_ACC | (L == 0 ? FL_RELU : 0));
    }

    split_f16<<<EW, 256>>>(pX, pFh, pFl);
    dim3 gf(TN2 / 128, TN2 / 128);
    adj_sigmoid<<<gf, 256, ADJ_SMEM>>>(pFh, pFl, out);
}

// round 10
// speedup vs baseline: 3.1149x; 1.2181x over previous
#include <cuda_runtime.h>
#include <cuda_fp16.h>
#include <mma.h>
#include <cstdint>
#include <math.h>

using namespace nvcuda;

#define NNODES 4096
#define TN2    8192
#define DIM    128
#define FDIM   256
#define NEDGE  65536

// ================= scratch (device globals; no allocation) =================
__device__ float g_X[TN2 * DIM];
__device__ float g_Kb[TN2 * DIM];
__device__ float g_Vb[TN2 * DIM];
__device__ float g_Qb[TN2 * DIM];
__device__ float g_F[TN2 * FDIM];
__device__ float g_AGG[TN2 * FDIM];
__device__ float g_MEAN[TN2 * FDIM];
__device__ float g_DEG[TN2];
__device__ float g_L[TN2];            // exp row sums
__device__ float g_OP[2 * TN2 * DIM]; // PV partials (2 key-halves)
__device__ __half g_Qh[TN2 * DIM];    // fp16(Q * isc)
__device__ __half g_Kh[TN2 * DIM];    // fp16(K)
__device__ __half g_Vth[DIM * TN2];   // fp16(V^T)
__device__ __half g_Fh[TN2 * DIM];    // fp16(final feats)

// ================= small elementwise kernels =================
__global__ void concat_x(const float* __restrict__ x1, const float* __restrict__ x2,
                         float* __restrict__ X) {
    int i = blockIdx.x * blockDim.x + threadIdx.x;
    if (i < TN2 * DIM) X[i] = (i < NNODES * DIM) ? x1[i] : x2[i - NNODES * DIM];
}
__global__ void zero_f(float* __restrict__ p, int n) {
    int i = blockIdx.x * blockDim.x + threadIdx.x;
    if (i < n) p[i] = 0.f;
}
__global__ void deg_count(const int* __restrict__ ei, int off, float* __restrict__ deg) {
    int e = blockIdx.x * blockDim.x + threadIdx.x;
    if (e < NEDGE) atomicAdd(&deg[ei[NEDGE + e] + off], 1.0f);
}
__global__ void scatter_add(const float* __restrict__ feats, const int* __restrict__ ei,
                            int off, float* __restrict__ agg) {
    int e = blockIdx.x;
    int src = ei[e] + off;
    int dst = ei[NEDGE + e] + off;
    atomicAdd(&agg[dst * FDIM + threadIdx.x], feats[src * FDIM + threadIdx.x]);
}
__global__ void mean_div(const float* __restrict__ agg, const float* __restrict__ deg,
                         float* __restrict__ mean) {
    int i = blockIdx.x * blockDim.x + threadIdx.x;
    if (i < TN2 * FDIM) mean[i] = agg[i] / fmaxf(deg[i >> 8], 1.0f);
}
__global__ void build_feats2(const float* __restrict__ X, const float* __restrict__ OP,
                             const float* __restrict__ l, float* __restrict__ F) {
    int i = blockIdx.x * blockDim.x + threadIdx.x;
    if (i < TN2 * DIM) {
        int row = i >> 7, c = i & 127;
        float x = X[i];
        float o = (OP[i] + OP[TN2 * DIM + i]) / l[row];
        F[row * FDIM + c] = x;
        F[row * FDIM + DIM + c] = x - o;
    }
}
// fused: Qh = fp16(Q*isc), Kh = fp16(K)
__global__ void round_qk_f16(const float* __restrict__ Q, const float* __restrict__ K,
                             __half* __restrict__ Qh, __half* __restrict__ Kh,
                             float isc) {
    int i = blockIdx.x * blockDim.x + threadIdx.x;
    if (i < TN2 * DIM) {
        Qh[i] = __float2half(Q[i] * isc);
        Kh[i] = __float2half(K[i]);
    }
}
__global__ void round_f16(const float* __restrict__ in, __half* __restrict__ out,
                          float mult) {
    int i = blockIdx.x * blockDim.x + threadIdx.x;
    if (i < TN2 * DIM) out[i] = __float2half(in[i] * mult);
}
// V [8192,128] fp32 -> Vt [128,8192] fp16 (64-key tiles)
__global__ void vt_round_f16(const float* __restrict__ V, __half* __restrict__ Vth) {
    __shared__ float t[64][132];
    int tid = threadIdx.x;
    int k0 = blockIdx.x * 64;
#pragma unroll
    for (int rep = 0; rep < 8; rep++) {
        int idx = rep * 256 + tid;
        int r = idx >> 5, c4 = (idx & 31) * 4;
        float4 v = *(const float4*)&V[(k0 + r) * DIM + c4];
        t[r][c4] = v.x; t[r][c4 + 1] = v.y; t[r][c4 + 2] = v.z; t[r][c4 + 3] = v.w;
    }
    __syncthreads();
    int d = tid >> 1, half_ = tid & 1;
    size_t base = (size_t)d * TN2 + k0 + half_ * 32;
#pragma unroll
    for (int j = 0; j < 32; j++)
        Vth[base + j] = __float2half(t[half_ * 32 + j][d]);
}

// ============ fp32 SIMT GEMM for small linears: C[M,128]=A[M,K]@B[K,128] ============
#define FL_RELU 1
#define FL_ACC  2
__global__ void gemm_n128(const float* __restrict__ A, const float* __restrict__ B,
                          const float* __restrict__ bias, float* __restrict__ C,
                          int K, int flags) {
    __shared__ float As[16 * 65];
    __shared__ float Bs[16 * 128];
    int tid = threadIdx.x;
    int tx = tid & 15, ty = tid >> 4;
    int m0 = blockIdx.x * 64;
    int arow = tid >> 2, akq = tid & 3;
    int brow = tid >> 5, bcol = (tid & 31) * 4;
    float acc[4][8];
#pragma unroll
    for (int i = 0; i < 4; i++)
#pragma unroll
        for (int j = 0; j < 8; j++) acc[i][j] = 0.f;
    for (int kt = 0; kt < K; kt += 16) {
        float4 av = *(const float4*)&A[(m0 + arow) * K + kt + akq * 4];
        As[(akq * 4 + 0) * 65 + arow] = av.x;
        As[(akq * 4 + 1) * 65 + arow] = av.y;
        As[(akq * 4 + 2) * 65 + arow] = av.z;
        As[(akq * 4 + 3) * 65 + arow] = av.w;
        *(float4*)&Bs[brow * 128 + bcol] = *(const float4*)&B[(kt + brow) * 128 + bcol];
        *(float4*)&Bs[(brow + 8) * 128 + bcol] = *(const float4*)&B[(kt + brow + 8) * 128 + bcol];
        __syncthreads();
#pragma unroll
        for (int kk = 0; kk < 16; kk++) {
            float a[4], b[8];
#pragma unroll
            for (int i = 0; i < 4; i++) a[i] = As[kk * 65 + ty + 16 * i];
#pragma unroll
            for (int j = 0; j < 8; j++) b[j] = Bs[kk * 128 + tx + 16 * j];
#pragma unroll
            for (int i = 0; i < 4; i++)
#pragma unroll
                for (int j = 0; j < 8; j++) acc[i][j] += a[i] * b[j];
        }
        __syncthreads();
    }
#pragma unroll
    for (int i = 0; i < 4; i++)
#pragma unroll
        for (int j = 0; j < 8; j++) {
            float v = acc[i][j];
            if (bias) v += bias[tx + 16 * j];
            int idx = (m0 + ty + 16 * i) * 128 + tx + 16 * j;
            if (flags & FL_ACC) v += C[idx];
            if (flags & FL_RELU) v = fmaxf(v, 0.f);
            C[idx] = v;
        }
}

// ======== fused flash attention: pure fp16 single-term ========
// grid (64 q-blocks, 2 key-halves), 256 threads = 8 warps, warp owns 16 query rows.
#define QSTR 136
#define VSTR 72
#define OFF_Q  0
#define OFF_K  (OFF_Q + 128 * QSTR)
#define OFF_V  (OFF_K + 64 * QSTR)
#define HB     ((OFF_V + 128 * VSTR) * 2)    // 70656 B
#define SB     (8 * 16 * 68 * 4)             // 34816 B
#define PB     (8 * 16 * 72 * 2)             // 18432 B
#define FL_SMEM (HB + SB + PB)               // 123904 B

__global__ __launch_bounds__(256, 1) void flash_f16(
    const __half* __restrict__ Qh, const __half* __restrict__ Kh,
    const __half* __restrict__ Vth, float* __restrict__ OP,
    float* __restrict__ lsum) {
    extern __shared__ char smc[];
    __half* sb = (__half*)smc;
    float* sS = (float*)(smc + HB);
    __half* sP = (__half*)(smc + HB + SB);

    int tid = threadIdx.x, lane = tid & 31, w = tid >> 5;
    int m0 = blockIdx.x * 128;
    int kh = blockIdx.y;
    int kbase = kh * (TN2 / 2);

    // stage Q [128 x 128]
#pragma unroll
    for (int rep = 0; rep < 8; rep++) {
        int u = rep * 256 + tid;
        int row = u >> 4, c8 = (u & 15) * 8;
        *(uint4*)&sb[OFF_Q + row * QSTR + c8] =
            *(const uint4*)&Qh[(size_t)(m0 + row) * DIM + c8];
    }

    wmma::fragment<wmma::accumulator, 16, 16, 16, float> oacc[8];
#pragma unroll
    for (int n = 0; n < 8; n++) wmma::fill_fragment(oacc[n], 0.f);
    float rs = 0.f;
    float* mS = sS + w * (16 * 68);
    __half* mP = sP + w * (16 * 72);

    for (int c = 0; c < 64; c++) {
        int kc = kbase + c * 64;
        __syncthreads();
        // stage K [64 keys x 128 dims]
#pragma unroll
        for (int rep = 0; rep < 4; rep++) {
            int u = rep * 256 + tid;
            int row = u >> 4, c8 = (u & 15) * 8;
            *(uint4*)&sb[OFF_K + row * QSTR + c8] =
                *(const uint4*)&Kh[(size_t)(kc + row) * DIM + c8];
        }
        // stage Vt [128 dims x 64 keys]
#pragma unroll
        for (int rep = 0; rep < 4; rep++) {
            int u = rep * 256 + tid;
            int row = u >> 3, c8 = (u & 7) * 8;
            *(uint4*)&sb[OFF_V + row * VSTR + c8] =
                *(const uint4*)&Vth[(size_t)row * TN2 + kc + c8];
        }
        __syncthreads();

        // S[16x64] = Q_w K^T
        wmma::fragment<wmma::accumulator, 16, 16, 16, float> sf[4];
#pragma unroll
        for (int n = 0; n < 4; n++) wmma::fill_fragment(sf[n], 0.f);
#pragma unroll
        for (int ks = 0; ks < 8; ks++) {
            wmma::fragment<wmma::matrix_a, 16, 16, 16, __half, wmma::row_major> a;
            wmma::load_matrix_sync(a, sb + OFF_Q + (w * 16) * QSTR + ks * 16, QSTR);
#pragma unroll
            for (int n = 0; n < 4; n++) {
                wmma::fragment<wmma::matrix_b, 16, 16, 16, __half, wmma::col_major> b;
                wmma::load_matrix_sync(b, sb + OFF_K + (n * 16) * QSTR + ks * 16, QSTR);
                wmma::mma_sync(sf[n], a, b, sf[n]);
            }
        }
#pragma unroll
        for (int n = 0; n < 4; n++)
            wmma::store_matrix_sync(mS + n * 16, sf[n], 68, wmma::mem_row_major);
        __syncwarp();

        // scalar: exp + rowsum + fp16 round (warp-private regions)
        {
            int r = lane >> 1, c0 = (lane & 1) * 32;
            float rsl = 0.f;
#pragma unroll
            for (int j = 0; j < 32; j++) {
                float e = __expf(mS[r * 68 + c0 + j]);
                rsl += e;
                mP[r * 72 + c0 + j] = __float2half(e);
            }
            rs += rsl;
        }
        __syncwarp();

        // O += P V
#pragma unroll
        for (int kt = 0; kt < 4; kt++) {
            wmma::fragment<wmma::matrix_a, 16, 16, 16, __half, wmma::row_major> pa;
            wmma::load_matrix_sync(pa, mP + kt * 16, 72);
#pragma unroll
            for (int n = 0; n < 8; n++) {
                wmma::fragment<wmma::matrix_b, 16, 16, 16, __half, wmma::col_major> v;
                wmma::load_matrix_sync(v, sb + OFF_V + (n * 16) * VSTR + kt * 16, VSTR);
                wmma::mma_sync(oacc[n], pa, v, oacc[n]);
            }
        }
    }

    // store O partial + row sums
    float* dst = OP + (size_t)kh * TN2 * DIM + (size_t)(m0 + w * 16) * DIM;
#pragma unroll
    for (int n = 0; n < 8; n++)
        wmma::store_matrix_sync(dst + n * 16, oacc[n], DIM, wmma::mem_row_major);
    rs += __shfl_xor_sync(0xffffffffu, rs, 1);
    if ((lane & 1) == 0) atomicAdd(&lsum[m0 + w * 16 + (lane >> 1)], rs);
}

// ======== fp16 NT GEMM + sigmoid: out = sigmoid(F F^T), K=128 staged whole ====
#define ASTR 136
#define ADJ_TILE (128 * ASTR)
#define ADJ_SMEM (2 * ADJ_TILE * 2)   // 69632 B -> 3 CTAs/SM

__global__ __launch_bounds__(256, 3) void adj_sigmoid(
    const __half* __restrict__ Fh, float* __restrict__ outF) {
    extern __shared__ __half smb[];
    int tid = threadIdx.x, w = tid >> 5;
    int wm = (w & 3) * 32, wn = (w >> 2) * 64;
    int m0 = blockIdx.x * 128, n0 = blockIdx.y * 128;
    __half* sA = smb;               // F rows m0
    __half* sB = smb + ADJ_TILE;    // F rows n0

#pragma unroll
    for (int rep = 0; rep < 8; rep++) {
        int u = rep * 256 + tid;
        int row = u >> 4, c8 = (u & 15) * 8;
        *(uint4*)&sA[row * ASTR + c8] = *(const uint4*)&Fh[(size_t)(m0 + row) * DIM + c8];
        *(uint4*)&sB[row * ASTR + c8] = *(const uint4*)&Fh[(size_t)(n0 + row) * DIM + c8];
    }
    __syncthreads();

    wmma::fragment<wmma::accumulator, 16, 16, 16, float> acc[2][4];
#pragma unroll
    for (int mt = 0; mt < 2; mt++)
#pragma unroll
        for (int nt = 0; nt < 4; nt++) wmma::fill_fragment(acc[mt][nt], 0.f);

#pragma unroll
    for (int ks = 0; ks < 8; ks++) {
        wmma::fragment<wmma::matrix_a, 16, 16, 16, __half, wmma::row_major> a[2];
#pragma unroll
        for (int mt = 0; mt < 2; mt++)
            wmma::load_matrix_sync(a[mt], sA + (wm + mt * 16) * ASTR + ks * 16, ASTR);
#pragma unroll
        for (int nt = 0; nt < 4; nt++) {
            wmma::fragment<wmma::matrix_b, 16, 16, 16, __half, wmma::col_major> b;
            wmma::load_matrix_sync(b, sB + (wn + nt * 16) * ASTR + ks * 16, ASTR);
#pragma unroll
            for (int mt = 0; mt < 2; mt++)
                wmma::mma_sync(acc[mt][nt], a[mt], b, acc[mt][nt]);
        }
    }

#pragma unroll
    for (int mt = 0; mt < 2; mt++)
#pragma unroll
        for (int nt = 0; nt < 4; nt++) {
#pragma unroll
            for (int i = 0; i < acc[mt][nt].num_elements; i++)
                acc[mt][nt].x[i] = 1.f / (1.f + __expf(-acc[mt][nt].x[i]));
            float* dst = outF + (size_t)(m0 + wm + mt * 16) * TN2 + n0 + wn + nt * 16;
            wmma::store_matrix_sync(dst, acc[mt][nt], TN2, wmma::mem_row_major);
        }
}

// ================= host orchestration =================
extern "C" void kernel_launch(void* const* d_in, const int* in_sizes, int n_in,
                              void* d_out, int out_size) {
    const float* x1 = (const float*)d_in[0];
    const float* x2 = (const float*)d_in[1];
    const int* ei1 = (const int*)d_in[2];
    const int* ei2 = (const int*)d_in[3];
    const float* Wk[2] = {(const float*)d_in[4], (const float*)d_in[13]};
    const float* bk[2] = {(const float*)d_in[5], (const float*)d_in[14]};
    const float* Wq[2] = {(const float*)d_in[6], (const float*)d_in[15]};
    const float* bq[2] = {(const float*)d_in[7], (const float*)d_in[16]};
    const float* Wv[2] = {(const float*)d_in[8], (const float*)d_in[17]};
    const float* bv[2] = {(const float*)d_in[9], (const float*)d_in[18]};
    const float* Wl[2] = {(const float*)d_in[10], (const float*)d_in[19]};
    const float* bl[2] = {(const float*)d_in[11], (const float*)d_in[20]};
    const float* Wr[2] = {(const float*)d_in[12], (const float*)d_in[21]};
    float* out = (float*)d_out;

    float *pX, *pK, *pV, *pQ, *pF, *pAGG, *pMEAN, *pDEG, *pL, *pOP;
    __half *pQh, *pKh, *pVth, *pFh;
    cudaGetSymbolAddress((void**)&pX, g_X);
    cudaGetSymbolAddress((void**)&pK, g_Kb);
    cudaGetSymbolAddress((void**)&pV, g_Vb);
    cudaGetSymbolAddress((void**)&pQ, g_Qb);
    cudaGetSymbolAddress((void**)&pF, g_F);
    cudaGetSymbolAddress((void**)&pAGG, g_AGG);
    cudaGetSymbolAddress((void**)&pMEAN, g_MEAN);
    cudaGetSymbolAddress((void**)&pDEG, g_DEG);
    cudaGetSymbolAddress((void**)&pL, g_L);
    cudaGetSymbolAddress((void**)&pOP, g_OP);
    cudaGetSymbolAddress((void**)&pQh, g_Qh);
    cudaGetSymbolAddress((void**)&pKh, g_Kh);
    cudaGetSymbolAddress((void**)&pVth, g_Vth);
    cudaGetSymbolAddress((void**)&pFh, g_Fh);

    cudaFuncSetAttribute(flash_f16, cudaFuncAttributeMaxDynamicSharedMemorySize, FL_SMEM);
    cudaFuncSetAttribute(adj_sigmoid, cudaFuncAttributeMaxDynamicSharedMemorySize, ADJ_SMEM);

    const float isc = 0.08838834764831845f;  // 1/sqrt(128)
    const int EW = (TN2 * DIM + 255) / 256;

    concat_x<<<EW, 256>>>(x1, x2, pX);
    zero_f<<<(TN2 + 255) / 256, 256>>>(pDEG, TN2);
    deg_count<<<(NEDGE + 255) / 256, 256>>>(ei1, 0, pDEG);
    deg_count<<<(NEDGE + 255) / 256, 256>>>(ei2, NNODES, pDEG);

    for (int L = 0; L < 2; L++) {
        gemm_n128<<<TN2 / 64, 256>>>(pX, Wk[L], bk[L], pK, 128, 0);
        gemm_n128<<<TN2 / 64, 256>>>(pX, Wv[L], bv[L], pV, 128, 0);
        gemm_n128<<<TN2 / 64, 256>>>(pX, Wq[L], bq[L], pQ, 128, 0);
        round_qk_f16<<<EW, 256>>>(pQ, pK, pQh, pKh, isc);
        vt_round_f16<<<TN2 / 64, 256>>>(pV, pVth);
        zero_f<<<(TN2 + 255) / 256, 256>>>(pL, TN2);
        dim3 gfl(TN2 / 128, 2);
        flash_f16<<<gfl, 256, FL_SMEM>>>(pQh, pKh, pVth, pOP, pL);
        build_feats2<<<EW, 256>>>(pX, pOP, pL, pF);
        zero_f<<<(TN2 * FDIM + 255) / 256, 256>>>(pAGG, TN2 * FDIM);
        scatter_add<<<NEDGE, FDIM>>>(pF, ei1, 0, pAGG);
        scatter_add<<<NEDGE, FDIM>>>(pF, ei2, NNODES, pAGG);
        mean_div<<<(TN2 * FDIM + 255) / 256, 256>>>(pAGG, pDEG, pMEAN);
        gemm_n128<<<TN2 / 64, 256>>>(pMEAN, Wl[L], bl[L], pX, 256, 0);
        gemm_n128<<<TN2 / 64, 256>>>(pF, Wr[L], nullptr, pX, 256,
                                     FL_ACC | (L == 0 ? FL_RELU : 0));
    }

    round_f16<<<EW, 256>>>(pX, pFh, 1.0f);
    dim3 gf(TN2 / 128, TN2 / 128);
    adj_sigmoid<<<gf, 256, ADJ_SMEM>>>(pFh, out);
}

// round 13
// speedup vs baseline: 3.5543x; 1.1411x over previous
#include <cuda_runtime.h>
#include <cuda_fp16.h>
#include <mma.h>
#include <cstdint>
#include <math.h>

using namespace nvcuda;

#define NNODES 4096
#define TN2    8192
#define DIM    128
#define FDIM   256
#define NEDGE  65536

// ================= scratch (device globals; no allocation) =================
__device__ float g_X[TN2 * DIM];
__device__ float g_Kb[TN2 * DIM];
__device__ float g_Vb[TN2 * DIM];
__device__ float g_Qb[TN2 * DIM];
__device__ float g_F[TN2 * FDIM];
__device__ float g_MEAN[TN2 * FDIM];
__device__ float g_L[TN2];            // exp row sums
__device__ float g_OP[2 * TN2 * DIM]; // PV partials (2 key-halves)
__device__ __half g_Qh[TN2 * DIM];    // fp16(Q * isc)
__device__ __half g_Kh[TN2 * DIM];    // fp16(K)
__device__ __half g_Vth[DIM * TN2];   // fp16(V^T)
__device__ __half g_Fh[TN2 * DIM];    // fp16(final feats)
// CSR for combined graph (both graphs, nodes 0..8191)
__device__ int g_cnt[TN2];
__device__ int g_off[TN2];
__device__ int g_cur[TN2];
__device__ int g_elist[2 * NEDGE];

// ================= small elementwise kernels =================
__global__ void concat_x(const float* __restrict__ x1, const float* __restrict__ x2,
                         float* __restrict__ X) {
    int i = blockIdx.x * blockDim.x + threadIdx.x;
    if (i < TN2 * DIM) X[i] = (i < NNODES * DIM) ? x1[i] : x2[i - NNODES * DIM];
}
__global__ void zero_f(float* __restrict__ p, int n) {
    int i = blockIdx.x * blockDim.x + threadIdx.x;
    if (i < n) p[i] = 0.f;
}
__global__ void zero_i(int* __restrict__ p, int n) {
    int i = blockIdx.x * blockDim.x + threadIdx.x;
    if (i < n) p[i] = 0;
}
// ---- CSR build (once; graph static across layers) ----
__global__ void edge_count(const int* __restrict__ ei, int off, int* __restrict__ cnt) {
    int e = blockIdx.x * blockDim.x + threadIdx.x;
    if (e < NEDGE) atomicAdd(&cnt[ei[NEDGE + e] + off], 1);
}
// exclusive scan of cnt[8192] -> off, single block of 1024 threads (8 elems each)
__global__ void scan_offsets(const int* __restrict__ cnt, int* __restrict__ off) {
    __shared__ int tsum[1024];
    int t = threadIdx.x;
    int local[8];
    int s = 0;
#pragma unroll
    for (int j = 0; j < 8; j++) { local[j] = s; s += cnt[t * 8 + j]; }
    tsum[t] = s;
    __syncthreads();
    for (int d = 1; d < 1024; d <<= 1) {
        int v = (t >= d) ? tsum[t - d] : 0;
        __syncthreads();
        tsum[t] += v;
        __syncthreads();
    }
    int base = (t == 0) ? 0 : tsum[t - 1];
#pragma unroll
    for (int j = 0; j < 8; j++) off[t * 8 + j] = base + local[j];
}
__global__ void fill_edges(const int* __restrict__ ei, int noff,
                           const int* __restrict__ off, int* __restrict__ cur,
                           int* __restrict__ elist) {
    int e = blockIdx.x * blockDim.x + threadIdx.x;
    if (e < NEDGE) {
        int src = ei[e] + noff;
        int dst = ei[NEDGE + e] + noff;
        int p = atomicAdd(&cur[dst], 1);
        elist[off[dst] + p] = src;
    }
}
// ---- gather-mean: MEAN[row] = sum_{src in N(row)} F[src] / max(deg,1) ----
__global__ void gather_mean(const float* __restrict__ F, const int* __restrict__ off,
                            const int* __restrict__ cnt, const int* __restrict__ elist,
                            float* __restrict__ mean) {
    int row = blockIdx.x;
    int c = threadIdx.x;
    int base = off[row], n = cnt[row];
    float s = 0.f;
    for (int i = 0; i < n; i++) {
        int src = elist[base + i];
        s += F[(size_t)src * FDIM + c];
    }
    mean[(size_t)row * FDIM + c] = s / (float)max(n, 1);
}
__global__ void build_feats2(const float* __restrict__ X, const float* __restrict__ OP,
                             const float* __restrict__ l, float* __restrict__ F) {
    int i = blockIdx.x * blockDim.x + threadIdx.x;
    if (i < TN2 * DIM) {
        int row = i >> 7, c = i & 127;
        float x = X[i];
        float o = (OP[i] + OP[TN2 * DIM + i]) / l[row];
        F[row * FDIM + c] = x;
        F[row * FDIM + DIM + c] = x - o;
    }
}
__global__ void round_qk_f16(const float* __restrict__ Q, const float* __restrict__ K,
                             __half* __restrict__ Qh, __half* __restrict__ Kh,
                             float isc) {
    int i = blockIdx.x * blockDim.x + threadIdx.x;
    if (i < TN2 * DIM) {
        Qh[i] = __float2half(Q[i] * isc);
        Kh[i] = __float2half(K[i]);
    }
}
__global__ void round_f16(const float* __restrict__ in, __half* __restrict__ out,
                          float mult) {
    int i = blockIdx.x * blockDim.x + threadIdx.x;
    if (i < TN2 * DIM) out[i] = __float2half(in[i] * mult);
}
// V [8192,128] fp32 -> Vt [128,8192] fp16 (64-key tiles)
__global__ void vt_round_f16(const float* __restrict__ V, __half* __restrict__ Vth) {
    __shared__ float t[64][132];
    int tid = threadIdx.x;
    int k0 = blockIdx.x * 64;
#pragma unroll
    for (int rep = 0; rep < 8; rep++) {
        int idx = rep * 256 + tid;
        int r = idx >> 5, c4 = (idx & 31) * 4;
        float4 v = *(const float4*)&V[(k0 + r) * DIM + c4];
        t[r][c4] = v.x; t[r][c4 + 1] = v.y; t[r][c4 + 2] = v.z; t[r][c4 + 3] = v.w;
    }
    __syncthreads();
    int d = tid >> 1, half_ = tid & 1;
    size_t base = (size_t)d * TN2 + k0 + half_ * 32;
#pragma unroll
    for (int j = 0; j < 32; j++)
        Vth[base + j] = __float2half(t[half_ * 32 + j][d]);
}

// ============ fp32 SIMT GEMM for small linears: C[M,128]=A[M,K]@B[K,128] ============
#define FL_RELU 1
#define FL_ACC  2
__global__ void gemm_n128(const float* __restrict__ A, const float* __restrict__ B,
                          const float* __restrict__ bias, float* __restrict__ C,
                          int K, int flags) {
    __shared__ float As[16 * 65];
    __shared__ float Bs[16 * 128];
    int tid = threadIdx.x;
    int tx = tid & 15, ty = tid >> 4;
    int m0 = blockIdx.x * 64;
    int arow = tid >> 2, akq = tid & 3;
    int brow = tid >> 5, bcol = (tid & 31) * 4;
    float acc[4][8];
#pragma unroll
    for (int i = 0; i < 4; i++)
#pragma unroll
        for (int j = 0; j < 8; j++) acc[i][j] = 0.f;
    for (int kt = 0; kt < K; kt += 16) {
        float4 av = *(const float4*)&A[(m0 + arow) * K + kt + akq * 4];
        As[(akq * 4 + 0) * 65 + arow] = av.x;
        As[(akq * 4 + 1) * 65 + arow] = av.y;
        As[(akq * 4 + 2) * 65 + arow] = av.z;
        As[(akq * 4 + 3) * 65 + arow] = av.w;
        *(float4*)&Bs[brow * 128 + bcol] = *(const float4*)&B[(kt + brow) * 128 + bcol];
        *(float4*)&Bs[(brow + 8) * 128 + bcol] = *(const float4*)&B[(kt + brow + 8) * 128 + bcol];
        __syncthreads();
#pragma unroll
        for (int kk = 0; kk < 16; kk++) {
            float a[4], b[8];
#pragma unroll
            for (int i = 0; i < 4; i++) a[i] = As[kk * 65 + ty + 16 * i];
#pragma unroll
            for (int j = 0; j < 8; j++) b[j] = Bs[kk * 128 + tx + 16 * j];
#pragma unroll
            for (int i = 0; i < 4; i++)
#pragma unroll
                for (int j = 0; j < 8; j++) acc[i][j] += a[i] * b[j];
        }
        __syncthreads();
    }
#pragma unroll
    for (int i = 0; i < 4; i++)
#pragma unroll
        for (int j = 0; j < 8; j++) {
            float v = acc[i][j];
            if (bias) v += bias[tx + 16 * j];
            int idx = (m0 + ty + 16 * i) * 128 + tx + 16 * j;
            if (flags & FL_ACC) v += C[idx];
            if (flags & FL_RELU) v = fmaxf(v, 0.f);
            C[idx] = v;
        }
}

// ======== fused flash attention: pure fp16 single-term (R10-proven version) ========
// grid (64 q-blocks, 2 key-halves), 256 threads = 8 warps, warp owns 16 query rows.
#define QSTR 136
#define VSTR 72
#define OFF_Q  0
#define OFF_K  (OFF_Q + 128 * QSTR)
#define OFF_V  (OFF_K + 64 * QSTR)
#define HB     ((OFF_V + 128 * VSTR) * 2)    // 70656 B
#define SB     (8 * 16 * 68 * 4)             // 34816 B
#define PB     (8 * 16 * 72 * 2)             // 18432 B
#define FL_SMEM (HB + SB + PB)               // 123904 B

__global__ __launch_bounds__(256, 1) void flash_f16(
    const __half* __restrict__ Qh, const __half* __restrict__ Kh,
    const __half* __restrict__ Vth, float* __restrict__ OP,
    float* __restrict__ lsum) {
    extern __shared__ char smc[];
    __half* sb = (__half*)smc;
    float* sS = (float*)(smc + HB);
    __half* sP = (__half*)(smc + HB + SB);

    int tid = threadIdx.x, lane = tid & 31, w = tid >> 5;
    int m0 = blockIdx.x * 128;
    int kh = blockIdx.y;
    int kbase = kh * (TN2 / 2);

    // stage Q [128 x 128]
#pragma unroll
    for (int rep = 0; rep < 8; rep++) {
        int u = rep * 256 + tid;
        int row = u >> 4, c8 = (u & 15) * 8;
        *(uint4*)&sb[OFF_Q + row * QSTR + c8] =
            *(const uint4*)&Qh[(size_t)(m0 + row) * DIM + c8];
    }

    wmma::fragment<wmma::accumulator, 16, 16, 16, float> oacc[8];
#pragma unroll
    for (int n = 0; n < 8; n++) wmma::fill_fragment(oacc[n], 0.f);
    float rs = 0.f;
    float* mS = sS + w * (16 * 68);
    __half* mP = sP + w * (16 * 72);

    for (int c = 0; c < 64; c++) {
        int kc = kbase + c * 64;
        __syncthreads();
        // stage K [64 keys x 128 dims]
#pragma unroll
        for (int rep = 0; rep < 4; rep++) {
            int u = rep * 256 + tid;
            int row = u >> 4, c8 = (u & 15) * 8;
            *(uint4*)&sb[OFF_K + row * QSTR + c8] =
                *(const uint4*)&Kh[(size_t)(kc + row) * DIM + c8];
        }
        // stage Vt [128 dims x 64 keys]
#pragma unroll
        for (int rep = 0; rep < 4; rep++) {
            int u = rep * 256 + tid;
            int row = u >> 3, c8 = (u & 7) * 8;
            *(uint4*)&sb[OFF_V + row * VSTR + c8] =
                *(const uint4*)&Vth[(size_t)row * TN2 + kc + c8];
        }
        __syncthreads();

        // S[16x64] = Q_w K^T
        wmma::fragment<wmma::accumulator, 16, 16, 16, float> sf[4];
#pragma unroll
        for (int n = 0; n < 4; n++) wmma::fill_fragment(sf[n], 0.f);
#pragma unroll
        for (int ks = 0; ks < 8; ks++) {
            wmma::fragment<wmma::matrix_a, 16, 16, 16, __half, wmma::row_major> a;
            wmma::load_matrix_sync(a, sb + OFF_Q + (w * 16) * QSTR + ks * 16, QSTR);
#pragma unroll
            for (int n = 0; n < 4; n++) {
                wmma::fragment<wmma::matrix_b, 16, 16, 16, __half, wmma::col_major> b;
                wmma::load_matrix_sync(b, sb + OFF_K + (n * 16) * QSTR + ks * 16, QSTR);
                wmma::mma_sync(sf[n], a, b, sf[n]);
            }
        }
#pragma unroll
        for (int n = 0; n < 4; n++)
            wmma::store_matrix_sync(mS + n * 16, sf[n], 68, wmma::mem_row_major);
        __syncwarp();

        // scalar: exp + rowsum + fp16 round (warp-private regions)
        {
            int r = lane >> 1, c0 = (lane & 1) * 32;
            float rsl = 0.f;
#pragma unroll
            for (int j = 0; j < 32; j++) {
                float e = __expf(mS[r * 68 + c0 + j]);
                rsl += e;
                mP[r * 72 + c0 + j] = __float2half(e);
            }
            rs += rsl;
        }
        __syncwarp();

        // O += P V
#pragma unroll
        for (int kt = 0; kt < 4; kt++) {
            wmma::fragment<wmma::matrix_a, 16, 16, 16, __half, wmma::row_major> pa;
            wmma::load_matrix_sync(pa, mP + kt * 16, 72);
#pragma unroll
            for (int n = 0; n < 8; n++) {
                wmma::fragment<wmma::matrix_b, 16, 16, 16, __half, wmma::col_major> v;
                wmma::load_matrix_sync(v, sb + OFF_V + (n * 16) * VSTR + kt * 16, VSTR);
                wmma::mma_sync(oacc[n], pa, v, oacc[n]);
            }
        }
    }

    // store O partial + row sums
    float* dst = OP + (size_t)kh * TN2 * DIM + (size_t)(m0 + w * 16) * DIM;
#pragma unroll
    for (int n = 0; n < 8; n++)
        wmma::store_matrix_sync(dst + n * 16, oacc[n], DIM, wmma::mem_row_major);
    rs += __shfl_xor_sync(0xffffffffu, rs, 1);
    if ((lane & 1) == 0) atomicAdd(&lsum[m0 + w * 16 + (lane >> 1)], rs);
}

// ======== fp16 NT GEMM + sigmoid: out = sigmoid(F F^T), K=128 staged whole ====
#define ASTR 136
#define ADJ_TILE (128 * ASTR)
#define ADJ_SMEM (2 * ADJ_TILE * 2)   // 69632 B -> 3 CTAs/SM

__global__ __launch_bounds__(256, 3) void adj_sigmoid(
    const __half* __restrict__ Fh, float* __restrict__ outF) {
    extern __shared__ __half smb[];
    int tid = threadIdx.x, w = tid >> 5;
    int wm = (w & 3) * 32, wn = (w >> 2) * 64;
    int m0 = blockIdx.x * 128, n0 = blockIdx.y * 128;
    __half* sA = smb;
    __half* sB = smb + ADJ_TILE;

#pragma unroll
    for (int rep = 0; rep < 8; rep++) {
        int u = rep * 256 + tid;
        int row = u >> 4, c8 = (u & 15) * 8;
        *(uint4*)&sA[row * ASTR + c8] = *(const uint4*)&Fh[(size_t)(m0 + row) * DIM + c8];
        *(uint4*)&sB[row * ASTR + c8] = *(const uint4*)&Fh[(size_t)(n0 + row) * DIM + c8];
    }
    __syncthreads();

    wmma::fragment<wmma::accumulator, 16, 16, 16, float> acc[2][4];
#pragma unroll
    for (int mt = 0; mt < 2; mt++)
#pragma unroll
        for (int nt = 0; nt < 4; nt++) wmma::fill_fragment(acc[mt][nt], 0.f);

#pragma unroll
    for (int ks = 0; ks < 8; ks++) {
        wmma::fragment<wmma::matrix_a, 16, 16, 16, __half, wmma::row_major> a[2];
#pragma unroll
        for (int mt = 0; mt < 2; mt++)
            wmma::load_matrix_sync(a[mt], sA + (wm + mt * 16) * ASTR + ks * 16, ASTR);
#pragma unroll
        for (int nt = 0; nt < 4; nt++) {
            wmma::fragment<wmma::matrix_b, 16, 16, 16, __half, wmma::col_major> b;
            wmma::load_matrix_sync(b, sB + (wn + nt * 16) * ASTR + ks * 16, ASTR);
#pragma unroll
            for (int mt = 0; mt < 2; mt++)
                wmma::mma_sync(acc[mt][nt], a[mt], b, acc[mt][nt]);
        }
    }

#pragma unroll
    for (int mt = 0; mt < 2; mt++)
#pragma unroll
        for (int nt = 0; nt < 4; nt++) {
#pragma unroll
            for (int i = 0; i < acc[mt][nt].num_elements; i++)
                acc[mt][nt].x[i] = 1.f / (1.f + __expf(-acc[mt][nt].x[i]));
            float* dst = outF + (size_t)(m0 + wm + mt * 16) * TN2 + n0 + wn + nt * 16;
            wmma::store_matrix_sync(dst, acc[mt][nt], TN2, wmma::mem_row_major);
        }
}

// ================= host orchestration =================
extern "C" void kernel_launch(void* const* d_in, const int* in_sizes, int n_in,
                              void* d_out, int out_size) {
    const float* x1 = (const float*)d_in[0];
    const float* x2 = (const float*)d_in[1];
    const int* ei1 = (const int*)d_in[2];
    const int* ei2 = (const int*)d_in[3];
    const float* Wk[2] = {(const float*)d_in[4], (const float*)d_in[13]};
    const float* bk[2] = {(const float*)d_in[5], (const float*)d_in[14]};
    const float* Wq[2] = {(const float*)d_in[6], (const float*)d_in[15]};
    const float* bq[2] = {(const float*)d_in[7], (const float*)d_in[16]};
    const float* Wv[2] = {(const float*)d_in[8], (const float*)d_in[17]};
    const float* bv[2] = {(const float*)d_in[9], (const float*)d_in[18]};
    const float* Wl[2] = {(const float*)d_in[10], (const float*)d_in[19]};
    const float* bl[2] = {(const float*)d_in[11], (const float*)d_in[20]};
    const float* Wr[2] = {(const float*)d_in[12], (const float*)d_in[21]};
    float* out = (float*)d_out;

    float *pX, *pK, *pV, *pQ, *pF, *pMEAN, *pL, *pOP;
    __half *pQh, *pKh, *pVth, *pFh;
    int *pCnt, *pOff, *pCur, *pEl;
    cudaGetSymbolAddress((void**)&pX, g_X);
    cudaGetSymbolAddress((void**)&pK, g_Kb);
    cudaGetSymbolAddress((void**)&pV, g_Vb);
    cudaGetSymbolAddress((void**)&pQ, g_Qb);
    cudaGetSymbolAddress((void**)&pF, g_F);
    cudaGetSymbolAddress((void**)&pMEAN, g_MEAN);
    cudaGetSymbolAddress((void**)&pL, g_L);
    cudaGetSymbolAddress((void**)&pOP, g_OP);
    cudaGetSymbolAddress((void**)&pQh, g_Qh);
    cudaGetSymbolAddress((void**)&pKh, g_Kh);
    cudaGetSymbolAddress((void**)&pVth, g_Vth);
    cudaGetSymbolAddress((void**)&pFh, g_Fh);
    cudaGetSymbolAddress((void**)&pCnt, g_cnt);
    cudaGetSymbolAddress((void**)&pOff, g_off);
    cudaGetSymbolAddress((void**)&pCur, g_cur);
    cudaGetSymbolAddress((void**)&pEl, g_elist);

    cudaFuncSetAttribute(flash_f16, cudaFuncAttributeMaxDynamicSharedMemorySize, FL_SMEM);
    cudaFuncSetAttribute(adj_sigmoid, cudaFuncAttributeMaxDynamicSharedMemorySize, ADJ_SMEM);

    const float isc = 0.08838834764831845f;  // 1/sqrt(128)
    const int EW = (TN2 * DIM + 255) / 256;

    concat_x<<<EW, 256>>>(x1, x2, pX);
    // ---- build CSR once ----
    zero_i<<<(TN2 + 255) / 256, 256>>>(pCnt, TN2);
    zero_i<<<(TN2 + 255) / 256, 256>>>(pCur, TN2);
    edge_count<<<(NEDGE + 255) / 256, 256>>>(ei1, 0, pCnt);
    edge_count<<<(NEDGE + 255) / 256, 256>>>(ei2, NNODES, pCnt);
    scan_offsets<<<1, 1024>>>(pCnt, pOff);
    fill_edges<<<(NEDGE + 255) / 256, 256>>>(ei1, 0, pOff, pCur, pEl);
    fill_edges<<<(NEDGE + 255) / 256, 256>>>(ei2, NNODES, pOff, pCur, pEl);

    for (int L = 0; L < 2; L++) {
        gemm_n128<<<TN2 / 64, 256>>>(pX, Wk[L], bk[L], pK, 128, 0);
        gemm_n128<<<TN2 / 64, 256>>>(pX, Wv[L], bv[L], pV, 128, 0);
        gemm_n128<<<TN2 / 64, 256>>>(pX, Wq[L], bq[L], pQ, 128, 0);
        round_qk_f16<<<EW, 256>>>(pQ, pK, pQh, pKh, isc);
        vt_round_f16<<<TN2 / 64, 256>>>(pV, pVth);
        zero_f<<<(TN2 + 255) / 256, 256>>>(pL, TN2);
        dim3 gfl(TN2 / 128, 2);
        flash_f16<<<gfl, 256, FL_SMEM>>>(pQh, pKh, pVth, pOP, pL);
        build_feats2<<<EW, 256>>>(pX, pOP, pL, pF);
        gather_mean<<<TN2, FDIM>>>(pF, pOff, pCnt, pEl, pMEAN);
        gemm_n128<<<TN2 / 64, 256>>>(pMEAN, Wl[L], bl[L], pX, 256, 0);
        gemm_n128<<<TN2 / 64, 256>>>(pF, Wr[L], nullptr, pX, 256,
                                     FL_ACC | (L == 0 ? FL_RELU : 0));
    }

    round_f16<<<EW, 256>>>(pX, pFh, 1.0f);
    dim3 gf(TN2 / 128, TN2 / 128);
    adj_sigmoid<<<gf, 256, ADJ_SMEM>>>(pFh, out);
}